// round 13
// baseline (speedup 1.0000x reference)
#include <cuda_runtime.h>
#include <cuda_bf16.h>
#include <math.h>

typedef unsigned long long ull;
typedef __nv_bfloat16 bf16;

#define D_IN  1024
#define NEXP  8
#define HID   4096
#define H2    8192
#define NTOK  4096
#define PMAX  9216     // 8192 pairs + per-expert padding to 128

// GEMM tiling: 256 threads, K-chunk 64 (128B rows = SW128 atom)
#define TM    128
#define KC    64
#define A_TILE 16384          // 128 rows * 128B
#define B_TILE 32768          // 256 rows * 128B
#define STAGE  (2*A_TILE + 2*B_TILE)   // 96KB
#define SMEM_GEMM (2 * STAGE)          // 192KB double buffer

// ---------------- scratch (static device memory: allowed) ----------------
__device__ float g_yp[(size_t)PMAX * D_IN];   // per-pair expert out fp32
__device__ bf16 g_xh[(size_t)PMAX * D_IN];
__device__ bf16 g_xl[(size_t)PMAX * D_IN];
__device__ bf16 g_ah[(size_t)PMAX * HID];
__device__ bf16 g_al[(size_t)PMAX * HID];
__device__ bf16 g_w1h[(size_t)NEXP * H2 * D_IN];
__device__ bf16 g_w1l[(size_t)NEXP * H2 * D_IN];
__device__ bf16 g_w2h[(size_t)NEXP * D_IN * HID];
__device__ bf16 g_w2l[(size_t)NEXP * D_IN * HID];
__device__ float g_probs[NTOK * NEXP];
__device__ int   g_top_idx[NTOK * 2];
__device__ float g_top_w[NTOK * 2];
__device__ int   g_counts[NEXP];
__device__ int   g_cursor[NEXP];
__device__ int   g_off[NEXP + 1];
__device__ int   g_pair_token[PMAX];
__device__ int   g_pair_slot[NTOK * 2];

// ---------------- PTX helpers (baseline sm_80+, safe for sm_103 target) --
__device__ __forceinline__ unsigned smem_u32(const void* p) {
    unsigned a;
    asm("{ .reg .u64 t; cvta.to.shared.u64 t, %1; cvt.u32.u64 %0, t; }" : "=r"(a) : "l"(p));
    return a;
}
__device__ __forceinline__ void cpa16(unsigned dst, const void* src) {
    asm volatile("cp.async.cg.shared.global [%0], [%1], 16;" :: "r"(dst), "l"(src));
}
__device__ __forceinline__ void ldm4(unsigned* r, unsigned addr) {
    asm volatile("ldmatrix.sync.aligned.m8n8.x4.shared.b16 {%0,%1,%2,%3}, [%4];"
                 : "=r"(r[0]), "=r"(r[1]), "=r"(r[2]), "=r"(r[3]) : "r"(addr));
}
#define MMA(d, a, b) \
    asm volatile("mma.sync.aligned.m16n8k16.row.col.f32.bf16.bf16.f32 " \
        "{%0,%1,%2,%3}, {%4,%5,%6,%7}, {%8,%9}, {%0,%1,%2,%3};" \
        : "+f"((d)[0]), "+f"((d)[1]), "+f"((d)[2]), "+f"((d)[3]) \
        : "r"((a)[0]), "r"((a)[1]), "r"((a)[2]), "r"((a)[3]), "r"((b)[0]), "r"((b)[1]))

__device__ __forceinline__ unsigned sw128(unsigned bo) { return bo ^ ((bo >> 3) & 0x70); }

__device__ __forceinline__ void split_store4(float4 v, __nv_bfloat162* hi, __nv_bfloat162* lo) {
    bf16 h0 = __float2bfloat16(v.x), h1 = __float2bfloat16(v.y);
    bf16 h2 = __float2bfloat16(v.z), h3 = __float2bfloat16(v.w);
    hi[0] = __halves2bfloat162(h0, h1);
    hi[1] = __halves2bfloat162(h2, h3);
    lo[0] = __floats2bfloat162_rn(v.x - __bfloat162float(h0), v.y - __bfloat162float(h1));
    lo[1] = __floats2bfloat162_rn(v.z - __bfloat162float(h2), v.w - __bfloat162float(h3));
}
__device__ __forceinline__ void split2(float a0, float a1,
                                       __nv_bfloat162* ph, __nv_bfloat162* pl) {
    bf16 h0 = __float2bfloat16(a0), h1 = __float2bfloat16(a1);
    *ph = __halves2bfloat162(h0, h1);
    *pl = __floats2bfloat162_rn(a0 - __bfloat162float(h0), a1 - __bfloat162float(h1));
}
__device__ __forceinline__ float silu(float g) { return g / (1.f + expf(-g)); }

// ---------------- 1. init ----------------
__global__ void init_k() {
    int i = blockIdx.x * blockDim.x + threadIdx.x;
    if (i < NEXP) { g_counts[i] = 0; g_cursor[i] = 0; }
    if (i < PMAX) g_pair_token[i] = -1;
}

// ---------------- 2. gate ----------------
__global__ void gate_k(const float* __restrict__ x, const float* __restrict__ Wg) {
    int t    = (blockIdx.x * blockDim.x + threadIdx.x) >> 5;
    int lane = threadIdx.x & 31;
    if (t >= NTOK) return;
    const float* xr = x + (size_t)t * D_IN;
    float acc[NEXP];
#pragma unroll
    for (int e = 0; e < NEXP; e++) acc[e] = 0.f;
    for (int d = lane; d < D_IN; d += 32) {
        float xv = xr[d];
        const float* wr = Wg + d * NEXP;
#pragma unroll
        for (int e = 0; e < NEXP; e++) acc[e] = fmaf(xv, wr[e], acc[e]);
    }
#pragma unroll
    for (int off = 16; off; off >>= 1)
#pragma unroll
        for (int e = 0; e < NEXP; e++)
            acc[e] += __shfl_down_sync(0xffffffffu, acc[e], off);
    if (lane == 0) {
        int e0 = 0; float v0 = acc[0];
#pragma unroll
        for (int e = 1; e < NEXP; e++) if (acc[e] > v0) { v0 = acc[e]; e0 = e; }
        int e1 = -1; float v1 = -1e30f;
#pragma unroll
        for (int e = 0; e < NEXP; e++) if (e != e0 && acc[e] > v1) { v1 = acc[e]; e1 = e; }
        float ew = expf(v1 - v0);
        float inv = 1.f / (1.f + ew);
        g_top_idx[t * 2]     = e0;
        g_top_idx[t * 2 + 1] = e1;
        g_top_w[t * 2]       = inv;
        g_top_w[t * 2 + 1]   = ew * inv;
        float p[NEXP], s = 0.f;
#pragma unroll
        for (int e = 0; e < NEXP; e++) { p[e] = expf(acc[e] - v0); s += p[e]; }
        float is = 1.f / s;
#pragma unroll
        for (int e = 0; e < NEXP; e++) g_probs[t * NEXP + e] = p[e] * is;
        atomicAdd(&g_counts[e0], 1);
        atomicAdd(&g_counts[e1], 1);
    }
}

// ---------------- 3. offsets ----------------
__global__ void off_k() {
    if (threadIdx.x == 0) {
        int o = 0;
#pragma unroll
        for (int e = 0; e < NEXP; e++) {
            g_off[e] = o;
            o += ((g_counts[e] + 127) >> 7) << 7;
        }
        g_off[NEXP] = o;
    }
}

// ---------------- 4. scatter ----------------
__global__ void scatter_k() {
    int i = blockIdx.x * blockDim.x + threadIdx.x;
    if (i >= NTOK * 2) return;
    int e = g_top_idx[i];
    int slot = g_off[e] + atomicAdd(&g_cursor[e], 1);
    g_pair_token[slot] = i >> 1;
    g_pair_slot[i] = slot;
}

// ---------------- 5a. gather x -> slot order, bf16 hi/lo ----------------
__global__ void gatherx_k(const float* __restrict__ x) {
    int idx = blockIdx.x * blockDim.x + threadIdx.x;    // PMAX * 256 float4
    int slot = idx >> 8;
    if (slot >= PMAX) return;
    int j = idx & 255;
    int tok = g_pair_token[slot];
    float4 v = make_float4(0.f, 0.f, 0.f, 0.f);
    if (tok >= 0) v = ((const float4*)x)[(size_t)tok * 256 + j];
    size_t o = (size_t)slot * 512 + j * 2;
    split_store4(v, (__nv_bfloat162*)g_xh + o, (__nv_bfloat162*)g_xl + o);
}

// ---------------- 5b. weight conversion (split so w2 overlaps gemm1) ----
__global__ void conv1_k(const float* __restrict__ w1) {
    size_t i = (size_t)blockIdx.x * blockDim.x + threadIdx.x;  // float4 index
    if (i >= (size_t)NEXP * H2 * D_IN / 4) return;
    float4 v = ((const float4*)w1)[i];
    split_store4(v, (__nv_bfloat162*)g_w1h + i * 2, (__nv_bfloat162*)g_w1l + i * 2);
}
__global__ void conv2_k(const float* __restrict__ w2) {
    size_t i = (size_t)blockIdx.x * blockDim.x + threadIdx.x;
    if (i >= (size_t)NEXP * D_IN * HID / 4) return;
    float4 v = ((const float4*)w2)[i];
    split_store4(v, (__nv_bfloat162*)g_w2h + i * 2, (__nv_bfloat162*)g_w2l + i * 2);
}

// ---------------- stage loaders: gmem bf16 -> SW128 SMEM via cp.async ----
__device__ __forceinline__ void stageA(unsigned smDst, const bf16* g, int stride, int tid) {
#pragma unroll
    for (int i = 0; i < 4; i++) {               // 128 rows * 8 segs = 1024
        int idx = (i << 8) | tid;
        int r = idx >> 3, s = idx & 7;
        unsigned bo = (unsigned)((r << 7) | (s << 4));
        cpa16(smDst + sw128(bo), g + (size_t)r * stride + (s << 3));
    }
}
__device__ __forceinline__ void stageB(unsigned smDst, const bf16* g, int stride, int tid) {
#pragma unroll
    for (int i = 0; i < 8; i++) {               // 256 rows * 8 segs = 2048
        int idx = (i << 8) | tid;
        int r = idx >> 3, s = idx & 7;
        unsigned bo = (unsigned)((r << 7) | (s << 4));
        cpa16(smDst + sw128(bo), g + (size_t)r * stride + (s << 3));
    }
}

// ---------------- 6. GEMM1 (fc1) fused with SiLU*val, bf16 3-split ------
// Per CTA: 128 rows x 128 act cols. B smem rows: [gate 0..127 ; val 128..255].
__global__ __launch_bounds__(256, 1)
void gemm1_fused(const float* __restrict__ bias) {
    extern __shared__ char smem[];
    const int rows_total = g_off[NEXP];
    const int row0 = blockIdx.y * TM;
    const int n0   = blockIdx.x * 128;          // act col base (0..4095)
    if (row0 >= rows_total) return;

    int e = 0;
#pragma unroll
    for (int i = 0; i < NEXP; i++) if (g_off[i + 1] <= row0) e = i + 1;

    const bf16* Ah  = g_xh + (size_t)row0 * D_IN;
    const bf16* Al  = g_xl + (size_t)row0 * D_IN;
    const size_t wbase = (size_t)e * H2 * D_IN + (size_t)n0 * D_IN;
    const bf16* Bgh = g_w1h + wbase;
    const bf16* Bvh = g_w1h + wbase + (size_t)HID * D_IN;
    const bf16* Bgl = g_w1l + wbase;
    const bf16* Bvl = g_w1l + wbase + (size_t)HID * D_IN;

    const int tid = threadIdx.x;
    const int lane = tid & 31, wid = tid >> 5;
    const int wm = (wid & 1) * 64;        // 2 warps in M
    const int wn = (wid >> 1) * 32;       // 4 warps in N
    const unsigned sb = smem_u32(smem);

    const unsigned aRow = wm + (lane & 15);
    const unsigned aKb  = (unsigned)(lane >> 4) << 4;
    const unsigned bRow = wn + (lane & 7) + ((unsigned)(lane >> 4) << 3);
    const unsigned bKb  = (unsigned)((lane >> 3) & 1) << 4;

    float accg[4][4][4], accv[4][4][4];
#pragma unroll
    for (int mi = 0; mi < 4; mi++)
#pragma unroll
        for (int ni = 0; ni < 4; ni++)
#pragma unroll
            for (int j = 0; j < 4; j++) { accg[mi][ni][j] = 0.f; accv[mi][ni][j] = 0.f; }

    const int T = D_IN / KC;   // 16

    // prologue: stage chunk 0 into buffer 0
    {
        unsigned s0 = sb;
        stageA(s0,              Ah,  D_IN, tid);
        stageA(s0 + A_TILE,     Al,  D_IN, tid);
        stageA(s0 + 2*A_TILE,            Bgh, D_IN, tid);
        stageA(s0 + 2*A_TILE + A_TILE,   Bvh, D_IN, tid);   // val at +128 rows
        stageA(s0 + 2*A_TILE + B_TILE,          Bgl, D_IN, tid);
        stageA(s0 + 2*A_TILE + B_TILE + A_TILE, Bvl, D_IN, tid);
        asm volatile("cp.async.commit_group;" ::: "memory");
    }

    for (int kt = 0; kt < T; kt++) {
        const int buf = kt & 1;
        asm volatile("cp.async.wait_group 0;" ::: "memory");
        __syncthreads();                       // data ready + prev reads of buf^1 done
        if (kt + 1 < T) {
            const int kOff = (kt + 1) * KC;
            unsigned s1 = sb + (buf ^ 1) * STAGE;
            stageA(s1,              Ah + kOff, D_IN, tid);
            stageA(s1 + A_TILE,     Al + kOff, D_IN, tid);
            stageA(s1 + 2*A_TILE,            Bgh + kOff, D_IN, tid);
            stageA(s1 + 2*A_TILE + A_TILE,   Bvh + kOff, D_IN, tid);
            stageA(s1 + 2*A_TILE + B_TILE,          Bgl + kOff, D_IN, tid);
            stageA(s1 + 2*A_TILE + B_TILE + A_TILE, Bvl + kOff, D_IN, tid);
            asm volatile("cp.async.commit_group;" ::: "memory");
        }

        const unsigned sAh = sb + buf * STAGE;
        const unsigned sAl = sAh + A_TILE;
        const unsigned sBh = sAl + A_TILE;     // 256 rows: gate then val
        const unsigned sBl = sBh + B_TILE;

#pragma unroll
        for (int ks = 0; ks < 4; ks++) {
            const unsigned kb = ks * 32;
            unsigned ra[4][4], rgh[2][4], rvh[2][4], rx[2][4];
#pragma unroll
            for (int mi = 0; mi < 4; mi++)
                ldm4(ra[mi], sAh + sw128((aRow + mi * 16) * 128 + kb + aKb));
#pragma unroll
            for (int g = 0; g < 2; g++) {
                ldm4(rgh[g], sBh + sw128((bRow + g * 16) * 128 + kb + bKb));
                ldm4(rvh[g], sBh + sw128((128 + bRow + g * 16) * 128 + kb + bKb));
            }
            // Ah*Bh (gate + val)
#pragma unroll
            for (int mi = 0; mi < 4; mi++)
#pragma unroll
                for (int ni = 0; ni < 4; ni++) {
                    MMA(accg[mi][ni], ra[mi], &rgh[ni >> 1][(ni & 1) * 2]);
                    MMA(accv[mi][ni], ra[mi], &rvh[ni >> 1][(ni & 1) * 2]);
                }
            // Ah*Bl
#pragma unroll
            for (int g = 0; g < 2; g++)
                ldm4(rx[g], sBl + sw128((bRow + g * 16) * 128 + kb + bKb));
#pragma unroll
            for (int mi = 0; mi < 4; mi++)
#pragma unroll
                for (int ni = 0; ni < 4; ni++)
                    MMA(accg[mi][ni], ra[mi], &rx[ni >> 1][(ni & 1) * 2]);
#pragma unroll
            for (int g = 0; g < 2; g++)
                ldm4(rx[g], sBl + sw128((128 + bRow + g * 16) * 128 + kb + bKb));
#pragma unroll
            for (int mi = 0; mi < 4; mi++)
#pragma unroll
                for (int ni = 0; ni < 4; ni++)
                    MMA(accv[mi][ni], ra[mi], &rx[ni >> 1][(ni & 1) * 2]);
            // Al*Bh  (reuse ra for Al frags)
#pragma unroll
            for (int mi = 0; mi < 4; mi++)
                ldm4(ra[mi], sAl + sw128((aRow + mi * 16) * 128 + kb + aKb));
#pragma unroll
            for (int mi = 0; mi < 4; mi++)
#pragma unroll
                for (int ni = 0; ni < 4; ni++) {
                    MMA(accg[mi][ni], ra[mi], &rgh[ni >> 1][(ni & 1) * 2]);
                    MMA(accv[mi][ni], ra[mi], &rvh[ni >> 1][(ni & 1) * 2]);
                }
        }
    }

    // epilogue: silu(g+bg)*(v+bv) -> bf16 hi/lo -> g_ah/g_al
    const float* bg = bias + (size_t)e * H2 + n0;
    const float* bvp = bg + HID;
    const int cr = lane >> 2;
    const int cc = (lane & 3) * 2;
#pragma unroll
    for (int mi = 0; mi < 4; mi++) {
        const int r0 = row0 + wm + mi * 16 + cr;
#pragma unroll
        for (int ni = 0; ni < 4; ni++) {
            const int col = wn + ni * 8 + cc;
            const float bg0 = bg[col], bg1 = bg[col + 1];
            const float bv0 = bvp[col], bv1 = bvp[col + 1];
            const size_t gc = (size_t)(n0 + col);
            {
                float a0 = silu(accg[mi][ni][0] + bg0) * (accv[mi][ni][0] + bv0);
                float a1 = silu(accg[mi][ni][1] + bg1) * (accv[mi][ni][1] + bv1);
                split2(a0, a1,
                       (__nv_bfloat162*)(g_ah + (size_t)r0 * HID + gc),
                       (__nv_bfloat162*)(g_al + (size_t)r0 * HID + gc));
            }
            {
                float a0 = silu(accg[mi][ni][2] + bg0) * (accv[mi][ni][2] + bv0);
                float a1 = silu(accg[mi][ni][3] + bg1) * (accv[mi][ni][3] + bv1);
                split2(a0, a1,
                       (__nv_bfloat162*)(g_ah + (size_t)(r0 + 8) * HID + gc),
                       (__nv_bfloat162*)(g_al + (size_t)(r0 + 8) * HID + gc));
            }
        }
    }
}

// ---------------- 7. GEMM2 (fc2): 128x256 tile, bf16 3-split ------------
__global__ __launch_bounds__(256, 1)
void gemm2_mma(const float* __restrict__ bias) {
    extern __shared__ char smem[];
    const int KDIM = HID, NCOLS = D_IN;
    const int rows_total = g_off[NEXP];
    const int row0 = blockIdx.y * TM;
    const int n0   = blockIdx.x * 256;
    if (row0 >= rows_total) return;

    int e = 0;
#pragma unroll
    for (int i = 0; i < NEXP; i++) if (g_off[i + 1] <= row0) e = i + 1;

    const bf16* Ah = g_ah + (size_t)row0 * KDIM;
    const bf16* Al = g_al + (size_t)row0 * KDIM;
    const bf16* Bh = g_w2h + (size_t)e * NCOLS * KDIM + (size_t)n0 * KDIM;
    const bf16* Bl = g_w2l + (size_t)e * NCOLS * KDIM + (size_t)n0 * KDIM;

    const int tid = threadIdx.x;
    const int lane = tid & 31, wid = tid >> 5;
    const int wm = (wid & 1) * 64;
    const int wn = (wid >> 1) * 64;
    const unsigned sb = smem_u32(smem);

    const unsigned aRow = wm + (lane & 15);
    const unsigned aKb  = (unsigned)(lane >> 4) << 4;
    const unsigned bRow = wn + (lane & 7) + ((unsigned)(lane >> 4) << 3);
    const unsigned bKb  = (unsigned)((lane >> 3) & 1) << 4;

    float acc[4][8][4];
#pragma unroll
    for (int mi = 0; mi < 4; mi++)
#pragma unroll
        for (int ni = 0; ni < 8; ni++)
#pragma unroll
            for (int j = 0; j < 4; j++) acc[mi][ni][j] = 0.f;

    const int T = KDIM / KC;   // 64

    {
        unsigned s0 = sb;
        stageA(s0,               Ah, KDIM, tid);
        stageA(s0 + A_TILE,      Al, KDIM, tid);
        stageB(s0 + 2 * A_TILE,  Bh, KDIM, tid);
        stageB(s0 + 2 * A_TILE + B_TILE, Bl, KDIM, tid);
        asm volatile("cp.async.commit_group;" ::: "memory");
    }

    for (int kt = 0; kt < T; kt++) {
        const int buf = kt & 1;
        asm volatile("cp.async.wait_group 0;" ::: "memory");
        __syncthreads();
        if (kt + 1 < T) {
            const int kOff = (kt + 1) * KC;
            unsigned s1 = sb + (buf ^ 1) * STAGE;
            stageA(s1,               Ah + kOff, KDIM, tid);
            stageA(s1 + A_TILE,      Al + kOff, KDIM, tid);
            stageB(s1 + 2 * A_TILE,  Bh + kOff, KDIM, tid);
            stageB(s1 + 2 * A_TILE + B_TILE, Bl + kOff, KDIM, tid);
            asm volatile("cp.async.commit_group;" ::: "memory");
        }

        const unsigned sAh = sb + buf * STAGE;
        const unsigned sAl = sAh + A_TILE;
        const unsigned sBh = sAl + A_TILE;
        const unsigned sBl = sBh + B_TILE;

#pragma unroll
        for (int ks = 0; ks < 4; ks++) {
            const unsigned kb = ks * 32;
            unsigned ra[4][4], rb[4][4], rc[4][4];
#pragma unroll
            for (int mi = 0; mi < 4; mi++)
                ldm4(ra[mi], sAh + sw128((aRow + mi * 16) * 128 + kb + aKb));
#pragma unroll
            for (int g = 0; g < 4; g++)
                ldm4(rb[g], sBh + sw128((bRow + g * 16) * 128 + kb + bKb));
#pragma unroll
            for (int mi = 0; mi < 4; mi++)
#pragma unroll
                for (int ni = 0; ni < 8; ni++)
                    MMA(acc[mi][ni], ra[mi], &rb[ni >> 1][(ni & 1) * 2]);
#pragma unroll
            for (int g = 0; g < 4; g++)
                ldm4(rc[g], sBl + sw128((bRow + g * 16) * 128 + kb + bKb));
#pragma unroll
            for (int mi = 0; mi < 4; mi++)
#pragma unroll
                for (int ni = 0; ni < 8; ni++)
                    MMA(acc[mi][ni], ra[mi], &rc[ni >> 1][(ni & 1) * 2]);
#pragma unroll
            for (int mi = 0; mi < 4; mi++)
                ldm4(ra[mi], sAl + sw128((aRow + mi * 16) * 128 + kb + aKb));
#pragma unroll
            for (int mi = 0; mi < 4; mi++)
#pragma unroll
                for (int ni = 0; ni < 8; ni++)
                    MMA(acc[mi][ni], ra[mi], &rb[ni >> 1][(ni & 1) * 2]);
        }
    }

    const float* brow = bias + (size_t)e * NCOLS + n0;
    const int cr = lane >> 2;
    const int cc = (lane & 3) * 2;
#pragma unroll
    for (int mi = 0; mi < 4; mi++) {
        const int r0 = row0 + wm + mi * 16 + cr;
#pragma unroll
        for (int ni = 0; ni < 8; ni++) {
            const int col = wn + ni * 8 + cc;
            const float b0 = brow[col], b1 = brow[col + 1];
            float* p0 = g_yp + (size_t)r0 * NCOLS + n0 + col;
            *(float2*)p0 = make_float2(acc[mi][ni][0] + b0, acc[mi][ni][1] + b1);
            float* p1 = p0 + (size_t)8 * NCOLS;
            *(float2*)p1 = make_float2(acc[mi][ni][2] + b0, acc[mi][ni][3] + b1);
        }
    }
}

// ---------------- 8. combine ----------------
__global__ void combine_k(float* __restrict__ out) {
    int idx = blockIdx.x * blockDim.x + threadIdx.x;
    if (idx >= NTOK * 256) return;
    int t = idx >> 8, j4 = idx & 255;
    int s0 = g_pair_slot[t * 2], s1 = g_pair_slot[t * 2 + 1];
    float w0 = g_top_w[t * 2], w1 = g_top_w[t * 2 + 1];
    float4 y0 = ((const float4*)g_yp)[(size_t)s0 * 256 + j4];
    float4 y1 = ((const float4*)g_yp)[(size_t)s1 * 256 + j4];
    float4 r;
    r.x = w0 * y0.x + w1 * y1.x;
    r.y = w0 * y0.y + w1 * y1.y;
    r.z = w0 * y0.z + w1 * y1.z;
    r.w = w0 * y0.w + w1 * y1.w;
    ((float4*)out)[idx] = r;
}

// ---------------- 9. aux loss ----------------
__global__ void aux_k(float* __restrict__ out, int out_size) {
    __shared__ float red[256];
    float local[NEXP];
#pragma unroll
    for (int e = 0; e < NEXP; e++) local[e] = 0.f;
    for (int t = threadIdx.x; t < NTOK; t += 256)
#pragma unroll
        for (int e = 0; e < NEXP; e++) local[e] += g_probs[t * NEXP + e];
    float aux = 0.f;
    for (int e = 0; e < NEXP; e++) {
        red[threadIdx.x] = local[e];
        __syncthreads();
        for (int s = 128; s; s >>= 1) {
            if (threadIdx.x < s) red[threadIdx.x] += red[threadIdx.x + s];
            __syncthreads();
        }
        if (threadIdx.x == 0)
            aux += ((float)g_counts[e] / (float)NTOK) * (red[0] / (float)NTOK);
        __syncthreads();
    }
    if (threadIdx.x == 0 && out_size > NTOK * D_IN)
        out[NTOK * D_IN] = (float)NEXP * aux;
}

// ---------------- launch ----------------
extern "C" void kernel_launch(void* const* d_in, const int* in_sizes, int n_in,
                              void* d_out, int out_size) {
    const float* x    = (const float*)d_in[0];
    const float* Wg   = (const float*)d_in[1];
    const float* fc1w = (const float*)d_in[2];
    const float* fc1b = (const float*)d_in[3];
    const float* fc2w = (const float*)d_in[4];
    const float* fc2b = (const float*)d_in[5];
    float* out = (float*)d_out;

    // one-time side-stream setup (runs on first, uncaptured, correctness call;
    // no device memory is allocated — streams/events are host objects)
    static cudaStream_t s2 = 0;
    static cudaEvent_t evFork = 0, evC1 = 0, evC2 = 0;
    static int s_ok = -1;
    if (s_ok < 0) {
        s_ok = (cudaStreamCreateWithFlags(&s2, cudaStreamNonBlocking) == cudaSuccess &&
                cudaEventCreateWithFlags(&evFork, cudaEventDisableTiming) == cudaSuccess &&
                cudaEventCreateWithFlags(&evC1, cudaEventDisableTiming) == cudaSuccess &&
                cudaEventCreateWithFlags(&evC2, cudaEventDisableTiming) == cudaSuccess) ? 1 : 0;
    }

    cudaFuncSetAttribute(gemm1_fused, cudaFuncAttributeMaxDynamicSharedMemorySize, SMEM_GEMM);
    cudaFuncSetAttribute(gemm2_mma,   cudaFuncAttributeMaxDynamicSharedMemorySize, SMEM_GEMM);

    const unsigned g1 = (unsigned)(((size_t)NEXP * H2 * D_IN / 4 + 255) / 256);
    const unsigned g2 = (unsigned)(((size_t)NEXP * D_IN * HID / 4 + 255) / 256);

    if (s_ok == 1) {
        // fork: weight conversions on s2, token routing on main stream
        cudaEventRecord(evFork, 0);
        cudaStreamWaitEvent(s2, evFork, 0);
        conv1_k<<<g1, 256, 0, s2>>>(fc1w);
        cudaEventRecord(evC1, s2);
        conv2_k<<<g2, 256, 0, s2>>>(fc2w);   // overlaps gemm1 on main stream
        cudaEventRecord(evC2, s2);

        init_k<<<(PMAX + 255) / 256, 256>>>();
        gate_k<<<NTOK / 4, 128>>>(x, Wg);
        off_k<<<1, 32>>>();
        scatter_k<<<(NTOK * 2 + 255) / 256, 256>>>();
        gatherx_k<<<PMAX, 256>>>(x);

        cudaStreamWaitEvent(0, evC1, 0);     // gemm1 needs w1 converted
        gemm1_fused<<<dim3(HID / 128, PMAX / TM), 256, SMEM_GEMM>>>(fc1b);
        cudaStreamWaitEvent(0, evC2, 0);     // gemm2 needs w2 converted
        gemm2_mma  <<<dim3(D_IN / 256, PMAX / TM), 256, SMEM_GEMM>>>(fc2b);
    } else {
        // fallback: fully serial on the capture stream
        conv1_k<<<g1, 256>>>(fc1w);
        conv2_k<<<g2, 256>>>(fc2w);
        init_k<<<(PMAX + 255) / 256, 256>>>();
        gate_k<<<NTOK / 4, 128>>>(x, Wg);
        off_k<<<1, 32>>>();
        scatter_k<<<(NTOK * 2 + 255) / 256, 256>>>();
        gatherx_k<<<PMAX, 256>>>(x);
        gemm1_fused<<<dim3(HID / 128, PMAX / TM), 256, SMEM_GEMM>>>(fc1b);
        gemm2_mma  <<<dim3(D_IN / 256, PMAX / TM), 256, SMEM_GEMM>>>(fc2b);
    }

    combine_k<<<(NTOK * 256) / 256, 256>>>(out);
    aux_k<<<1, 256>>>(out, out_size);
}

// round 14
// speedup vs baseline: 2.1528x; 2.1528x over previous
#include <cuda_runtime.h>
#include <cuda_fp16.h>
#include <math.h>

typedef unsigned long long ull;

#define D_IN  1024
#define NEXP  8
#define HID   4096
#define H2    8192
#define NTOK  4096
#define PMAX  9216     // 8192 pairs + per-expert padding to 128

// GEMM tiling: 256 threads, K-chunk 64 (128B rows = SW128 atom)
#define TM    128
#define KC    64
#define A_TILE 16384          // 128 rows * 128B
#define B_TILE 32768          // 256 rows * 128B
#define STAGE  (2*A_TILE + B_TILE)     // Ah, Al, B = 64KB
#define SMEM_GEMM (2 * STAGE)          // 128KB double buffer

// ---------------- scratch (static device memory: allowed) ----------------
__device__ float g_yp[(size_t)PMAX * D_IN];   // per-pair expert out fp32
__device__ __half g_xh[(size_t)PMAX * D_IN];
__device__ __half g_xl[(size_t)PMAX * D_IN];
__device__ __half g_ah[(size_t)PMAX * HID];
__device__ __half g_al[(size_t)PMAX * HID];
__device__ __half g_w1[(size_t)NEXP * H2 * D_IN];
__device__ __half g_w2[(size_t)NEXP * D_IN * HID];
__device__ float g_probs[NTOK * NEXP];
__device__ int   g_top_idx[NTOK * 2];
__device__ float g_top_w[NTOK * 2];
__device__ int   g_counts[NEXP];
__device__ int   g_cursor[NEXP];
__device__ int   g_off[NEXP + 1];
__device__ int   g_pair_token[PMAX];
__device__ int   g_pair_slot[NTOK * 2];

// ---------------- PTX helpers (baseline sm_80+, safe for sm_103 target) --
__device__ __forceinline__ unsigned smem_u32(const void* p) {
    unsigned a;
    asm("{ .reg .u64 t; cvta.to.shared.u64 t, %1; cvt.u32.u64 %0, t; }" : "=r"(a) : "l"(p));
    return a;
}
__device__ __forceinline__ void cpa16(unsigned dst, const void* src) {
    asm volatile("cp.async.cg.shared.global [%0], [%1], 16;" :: "r"(dst), "l"(src));
}
__device__ __forceinline__ void ldm4(unsigned* r, unsigned addr) {
    asm volatile("ldmatrix.sync.aligned.m8n8.x4.shared.b16 {%0,%1,%2,%3}, [%4];"
                 : "=r"(r[0]), "=r"(r[1]), "=r"(r[2]), "=r"(r[3]) : "r"(addr));
}
#define MMA(d, a, b) \
    asm volatile("mma.sync.aligned.m16n8k16.row.col.f32.f16.f16.f32 " \
        "{%0,%1,%2,%3}, {%4,%5,%6,%7}, {%8,%9}, {%0,%1,%2,%3};" \
        : "+f"((d)[0]), "+f"((d)[1]), "+f"((d)[2]), "+f"((d)[3]) \
        : "r"((a)[0]), "r"((a)[1]), "r"((a)[2]), "r"((a)[3]), "r"((b)[0]), "r"((b)[1]))

__device__ __forceinline__ unsigned sw128(unsigned bo) { return bo ^ ((bo >> 3) & 0x70); }

// fp32x4 -> fp16 hi/lo split (A-side: error ~2^-22, negligible)
__device__ __forceinline__ void split_store4h(float4 v, __half2* hi, __half2* lo) {
    __half h0 = __float2half_rn(v.x), h1 = __float2half_rn(v.y);
    __half h2 = __float2half_rn(v.z), h3 = __float2half_rn(v.w);
    hi[0] = __halves2half2(h0, h1);
    hi[1] = __halves2half2(h2, h3);
    lo[0] = __floats2half2_rn(v.x - __half2float(h0), v.y - __half2float(h1));
    lo[1] = __floats2half2_rn(v.z - __half2float(h2), v.w - __half2float(h3));
}
__device__ __forceinline__ void split2h(float a0, float a1, __half2* ph, __half2* pl) {
    __half h0 = __float2half_rn(a0), h1 = __float2half_rn(a1);
    *ph = __halves2half2(h0, h1);
    *pl = __floats2half2_rn(a0 - __half2float(h0), a1 - __half2float(h1));
}
__device__ __forceinline__ float silu(float g) { return g / (1.f + expf(-g)); }

// ---------------- 1. init ----------------
__global__ void init_k() {
    int i = blockIdx.x * blockDim.x + threadIdx.x;
    if (i < NEXP) { g_counts[i] = 0; g_cursor[i] = 0; }
    if (i < PMAX) g_pair_token[i] = -1;
}

// ---------------- 2. gate (smem-cached Wg, conflict-free) ----------------
__global__ __launch_bounds__(256)
void gate_k(const float* __restrict__ x, const float* __restrict__ Wg) {
    __shared__ float Wt[NEXP][D_IN];     // 32KB, transposed
    const int tid = threadIdx.x;
    for (int i = tid; i < D_IN * NEXP; i += 256) {
        int d = i >> 3, e = i & 7;
        Wt[e][d] = Wg[i];
    }
    __syncthreads();
    const int wid = tid >> 5, lane = tid & 31;
    const int t = blockIdx.x * 8 + wid;           // 512 blocks * 8 warps = NTOK
    const float* xr = x + (size_t)t * D_IN;
    float acc[NEXP];
#pragma unroll
    for (int e = 0; e < NEXP; e++) acc[e] = 0.f;
    for (int d = lane; d < D_IN; d += 32) {
        float xv = xr[d];
#pragma unroll
        for (int e = 0; e < NEXP; e++) acc[e] = fmaf(xv, Wt[e][d], acc[e]);
    }
#pragma unroll
    for (int off = 16; off; off >>= 1)
#pragma unroll
        for (int e = 0; e < NEXP; e++)
            acc[e] += __shfl_down_sync(0xffffffffu, acc[e], off);
    if (lane == 0) {
        int e0 = 0; float v0 = acc[0];
#pragma unroll
        for (int e = 1; e < NEXP; e++) if (acc[e] > v0) { v0 = acc[e]; e0 = e; }
        int e1 = -1; float v1 = -1e30f;
#pragma unroll
        for (int e = 0; e < NEXP; e++) if (e != e0 && acc[e] > v1) { v1 = acc[e]; e1 = e; }
        float ew = expf(v1 - v0);
        float inv = 1.f / (1.f + ew);
        g_top_idx[t * 2]     = e0;
        g_top_idx[t * 2 + 1] = e1;
        g_top_w[t * 2]       = inv;
        g_top_w[t * 2 + 1]   = ew * inv;
        float p[NEXP], s = 0.f;
#pragma unroll
        for (int e = 0; e < NEXP; e++) { p[e] = expf(acc[e] - v0); s += p[e]; }
        float is = 1.f / s;
#pragma unroll
        for (int e = 0; e < NEXP; e++) g_probs[t * NEXP + e] = p[e] * is;
        atomicAdd(&g_counts[e0], 1);
        atomicAdd(&g_counts[e1], 1);
    }
}

// ---------------- 3. offsets ----------------
__global__ void off_k() {
    if (threadIdx.x == 0) {
        int o = 0;
#pragma unroll
        for (int e = 0; e < NEXP; e++) {
            g_off[e] = o;
            o += ((g_counts[e] + 127) >> 7) << 7;
        }
        g_off[NEXP] = o;
    }
}

// ---------------- 4. scatter ----------------
__global__ void scatter_k() {
    int i = blockIdx.x * blockDim.x + threadIdx.x;
    if (i >= NTOK * 2) return;
    int e = g_top_idx[i];
    int slot = g_off[e] + atomicAdd(&g_cursor[e], 1);
    g_pair_token[slot] = i >> 1;
    g_pair_slot[i] = slot;
}

// ---------------- 5a. gather x -> slot order, fp16 hi/lo ----------------
__global__ void gatherx_k(const float* __restrict__ x) {
    int idx = blockIdx.x * blockDim.x + threadIdx.x;    // PMAX * 256 float4
    int slot = idx >> 8;
    if (slot >= PMAX) return;
    int j = idx & 255;
    int tok = g_pair_token[slot];
    float4 v = make_float4(0.f, 0.f, 0.f, 0.f);
    if (tok >= 0) v = ((const float4*)x)[(size_t)tok * 256 + j];
    size_t o = (size_t)slot * 512 + j * 2;
    split_store4h(v, (__half2*)g_xh + o, (__half2*)g_xl + o);
}

// ---------------- 5b. weight conversion fp32 -> fp16 (single) ----------
__global__ void conv_all(const float* __restrict__ w1, const float* __restrict__ w2) {
    const size_t N1 = (size_t)NEXP * H2 * D_IN / 4;
    size_t i = (size_t)blockIdx.x * blockDim.x + threadIdx.x;
    if (i < N1) {
        float4 v = ((const float4*)w1)[i];
        ((__half2*)g_w1)[i * 2]     = __floats2half2_rn(v.x, v.y);
        ((__half2*)g_w1)[i * 2 + 1] = __floats2half2_rn(v.z, v.w);
    } else {
        size_t j = i - N1;
        if (j >= (size_t)NEXP * D_IN * HID / 4) return;
        float4 v = ((const float4*)w2)[j];
        ((__half2*)g_w2)[j * 2]     = __floats2half2_rn(v.x, v.y);
        ((__half2*)g_w2)[j * 2 + 1] = __floats2half2_rn(v.z, v.w);
    }
}

// ---------------- stage loaders: gmem fp16 -> SW128 SMEM via cp.async ----
__device__ __forceinline__ void stageA(unsigned smDst, const __half* g, int stride, int tid) {
#pragma unroll
    for (int i = 0; i < 4; i++) {               // 128 rows * 8 segs = 1024
        int idx = (i << 8) | tid;
        int r = idx >> 3, s = idx & 7;
        unsigned bo = (unsigned)((r << 7) | (s << 4));
        cpa16(smDst + sw128(bo), g + (size_t)r * stride + (s << 3));
    }
}
__device__ __forceinline__ void stageB(unsigned smDst, const __half* g, int stride, int tid) {
#pragma unroll
    for (int i = 0; i < 8; i++) {               // 256 rows * 8 segs = 2048
        int idx = (i << 8) | tid;
        int r = idx >> 3, s = idx & 7;
        unsigned bo = (unsigned)((r << 7) | (s << 4));
        cpa16(smDst + sw128(bo), g + (size_t)r * stride + (s << 3));
    }
}

// ---------------- 6. GEMM1 (fc1) fused with SiLU*val, fp16 2-term -------
// Per CTA: 128 rows x 128 act cols. B smem rows: [gate 0..127 ; val 128..255].
__global__ __launch_bounds__(256, 1)
void gemm1_fused(const float* __restrict__ bias) {
    extern __shared__ char smem[];
    const int rows_total = g_off[NEXP];
    const int row0 = blockIdx.y * TM;
    const int n0   = blockIdx.x * 128;          // act col base (0..4095)
    if (row0 >= rows_total) return;

    int e = 0;
#pragma unroll
    for (int i = 0; i < NEXP; i++) if (g_off[i + 1] <= row0) e = i + 1;

    const __half* Ah = g_xh + (size_t)row0 * D_IN;
    const __half* Al = g_xl + (size_t)row0 * D_IN;
    const size_t wbase = (size_t)e * H2 * D_IN + (size_t)n0 * D_IN;
    const __half* Bg = g_w1 + wbase;
    const __half* Bv = g_w1 + wbase + (size_t)HID * D_IN;

    const int tid = threadIdx.x;
    const int lane = tid & 31, wid = tid >> 5;
    const int wm = (wid & 1) * 64;        // 2 warps in M
    const int wn = (wid >> 1) * 32;       // 4 warps in N
    const unsigned sb = smem_u32(smem);

    const unsigned aRow = wm + (lane & 15);
    const unsigned aKb  = (unsigned)(lane >> 4) << 4;
    const unsigned bRow = wn + (lane & 7) + ((unsigned)(lane >> 4) << 3);
    const unsigned bKb  = (unsigned)((lane >> 3) & 1) << 4;

    float accg[4][4][4], accv[4][4][4];
#pragma unroll
    for (int mi = 0; mi < 4; mi++)
#pragma unroll
        for (int ni = 0; ni < 4; ni++)
#pragma unroll
            for (int j = 0; j < 4; j++) { accg[mi][ni][j] = 0.f; accv[mi][ni][j] = 0.f; }

    const int T = D_IN / KC;   // 16

    // prologue: stage chunk 0 into buffer 0
    {
        unsigned s0 = sb;
        stageA(s0,              Ah, D_IN, tid);
        stageA(s0 + A_TILE,     Al, D_IN, tid);
        stageA(s0 + 2*A_TILE,           Bg, D_IN, tid);
        stageA(s0 + 2*A_TILE + 16384,   Bv, D_IN, tid);   // val at +128 rows
        asm volatile("cp.async.commit_group;" ::: "memory");
    }

    for (int kt = 0; kt < T; kt++) {
        const int buf = kt & 1;
        asm volatile("cp.async.wait_group 0;" ::: "memory");
        __syncthreads();                       // data ready + prev reads of buf^1 done
        if (kt + 1 < T) {
            const int kOff = (kt + 1) * KC;
            unsigned s1 = sb + (buf ^ 1) * STAGE;
            stageA(s1,              Ah + kOff, D_IN, tid);
            stageA(s1 + A_TILE,     Al + kOff, D_IN, tid);
            stageA(s1 + 2*A_TILE,           Bg + kOff, D_IN, tid);
            stageA(s1 + 2*A_TILE + 16384,   Bv + kOff, D_IN, tid);
            asm volatile("cp.async.commit_group;" ::: "memory");
        }

        const unsigned sAh = sb + buf * STAGE;
        const unsigned sAl = sAh + A_TILE;
        const unsigned sB  = sAl + A_TILE;     // 256 rows: gate then val

#pragma unroll
        for (int ks = 0; ks < 4; ks++) {
            const unsigned kb = ks * 32;
            unsigned ra[4][4], rg[2][4], rv[2][4];
#pragma unroll
            for (int mi = 0; mi < 4; mi++)
                ldm4(ra[mi], sAh + sw128((aRow + mi * 16) * 128 + kb + aKb));
#pragma unroll
            for (int g = 0; g < 2; g++) {
                ldm4(rg[g], sB + sw128((bRow + g * 16) * 128 + kb + bKb));
                ldm4(rv[g], sB + sw128((128 + bRow + g * 16) * 128 + kb + bKb));
            }
            // Ah*B (gate + val)
#pragma unroll
            for (int mi = 0; mi < 4; mi++)
#pragma unroll
                for (int ni = 0; ni < 4; ni++) {
                    MMA(accg[mi][ni], ra[mi], &rg[ni >> 1][(ni & 1) * 2]);
                    MMA(accv[mi][ni], ra[mi], &rv[ni >> 1][(ni & 1) * 2]);
                }
            // Al*B
#pragma unroll
            for (int mi = 0; mi < 4; mi++)
                ldm4(ra[mi], sAl + sw128((aRow + mi * 16) * 128 + kb + aKb));
#pragma unroll
            for (int mi = 0; mi < 4; mi++)
#pragma unroll
                for (int ni = 0; ni < 4; ni++) {
                    MMA(accg[mi][ni], ra[mi], &rg[ni >> 1][(ni & 1) * 2]);
                    MMA(accv[mi][ni], ra[mi], &rv[ni >> 1][(ni & 1) * 2]);
                }
        }
    }

    // epilogue: silu(g+bg)*(v+bv) -> fp16 hi/lo -> g_ah/g_al
    const float* bg = bias + (size_t)e * H2 + n0;
    const float* bvp = bg + HID;
    const int cr = lane >> 2;
    const int cc = (lane & 3) * 2;
#pragma unroll
    for (int mi = 0; mi < 4; mi++) {
        const int r0 = row0 + wm + mi * 16 + cr;
#pragma unroll
        for (int ni = 0; ni < 4; ni++) {
            const int col = wn + ni * 8 + cc;
            const float bg0 = bg[col], bg1 = bg[col + 1];
            const float bv0 = bvp[col], bv1 = bvp[col + 1];
            const size_t gc = (size_t)(n0 + col);
            {
                float a0 = silu(accg[mi][ni][0] + bg0) * (accv[mi][ni][0] + bv0);
                float a1 = silu(accg[mi][ni][1] + bg1) * (accv[mi][ni][1] + bv1);
                split2h(a0, a1,
                        (__half2*)(g_ah + (size_t)r0 * HID + gc),
                        (__half2*)(g_al + (size_t)r0 * HID + gc));
            }
            {
                float a0 = silu(accg[mi][ni][2] + bg0) * (accv[mi][ni][2] + bv0);
                float a1 = silu(accg[mi][ni][3] + bg1) * (accv[mi][ni][3] + bv1);
                split2h(a0, a1,
                        (__half2*)(g_ah + (size_t)(r0 + 8) * HID + gc),
                        (__half2*)(g_al + (size_t)(r0 + 8) * HID + gc));
            }
        }
    }
}

// ---------------- 7. GEMM2 (fc2): 128x256 tile, fp16 2-term -------------
__global__ __launch_bounds__(256, 1)
void gemm2_mma(const float* __restrict__ bias) {
    extern __shared__ char smem[];
    const int KDIM = HID, NCOLS = D_IN;
    const int rows_total = g_off[NEXP];
    const int row0 = blockIdx.y * TM;
    const int n0   = blockIdx.x * 256;
    if (row0 >= rows_total) return;

    int e = 0;
#pragma unroll
    for (int i = 0; i < NEXP; i++) if (g_off[i + 1] <= row0) e = i + 1;

    const __half* Ah = g_ah + (size_t)row0 * KDIM;
    const __half* Al = g_al + (size_t)row0 * KDIM;
    const __half* B  = g_w2 + (size_t)e * NCOLS * KDIM + (size_t)n0 * KDIM;

    const int tid = threadIdx.x;
    const int lane = tid & 31, wid = tid >> 5;
    const int wm = (wid & 1) * 64;
    const int wn = (wid >> 1) * 64;
    const unsigned sb = smem_u32(smem);

    const unsigned aRow = wm + (lane & 15);
    const unsigned aKb  = (unsigned)(lane >> 4) << 4;
    const unsigned bRow = wn + (lane & 7) + ((unsigned)(lane >> 4) << 3);
    const unsigned bKb  = (unsigned)((lane >> 3) & 1) << 4;

    float acc[4][8][4];
#pragma unroll
    for (int mi = 0; mi < 4; mi++)
#pragma unroll
        for (int ni = 0; ni < 8; ni++)
#pragma unroll
            for (int j = 0; j < 4; j++) acc[mi][ni][j] = 0.f;

    const int T = KDIM / KC;   // 64

    {
        unsigned s0 = sb;
        stageA(s0,              Ah, KDIM, tid);
        stageA(s0 + A_TILE,     Al, KDIM, tid);
        stageB(s0 + 2 * A_TILE, B,  KDIM, tid);
        asm volatile("cp.async.commit_group;" ::: "memory");
    }

    for (int kt = 0; kt < T; kt++) {
        const int buf = kt & 1;
        asm volatile("cp.async.wait_group 0;" ::: "memory");
        __syncthreads();
        if (kt + 1 < T) {
            const int kOff = (kt + 1) * KC;
            unsigned s1 = sb + (buf ^ 1) * STAGE;
            stageA(s1,              Ah + kOff, KDIM, tid);
            stageA(s1 + A_TILE,     Al + kOff, KDIM, tid);
            stageB(s1 + 2 * A_TILE, B + kOff,  KDIM, tid);
            asm volatile("cp.async.commit_group;" ::: "memory");
        }

        const unsigned sAh = sb + buf * STAGE;
        const unsigned sAl = sAh + A_TILE;
        const unsigned sB  = sAl + A_TILE;

#pragma unroll
        for (int ks = 0; ks < 4; ks++) {
            const unsigned kb = ks * 32;
            unsigned ra[4][4], rb[4][4];
#pragma unroll
            for (int mi = 0; mi < 4; mi++)
                ldm4(ra[mi], sAh + sw128((aRow + mi * 16) * 128 + kb + aKb));
#pragma unroll
            for (int g = 0; g < 4; g++)
                ldm4(rb[g], sB + sw128((bRow + g * 16) * 128 + kb + bKb));
#pragma unroll
            for (int mi = 0; mi < 4; mi++)
#pragma unroll
                for (int ni = 0; ni < 8; ni++)
                    MMA(acc[mi][ni], ra[mi], &rb[ni >> 1][(ni & 1) * 2]);
#pragma unroll
            for (int mi = 0; mi < 4; mi++)
                ldm4(ra[mi], sAl + sw128((aRow + mi * 16) * 128 + kb + aKb));
#pragma unroll
            for (int mi = 0; mi < 4; mi++)
#pragma unroll
                for (int ni = 0; ni < 8; ni++)
                    MMA(acc[mi][ni], ra[mi], &rb[ni >> 1][(ni & 1) * 2]);
        }
    }

    const float* brow = bias + (size_t)e * NCOLS + n0;
    const int cr = lane >> 2;
    const int cc = (lane & 3) * 2;
#pragma unroll
    for (int mi = 0; mi < 4; mi++) {
        const int r0 = row0 + wm + mi * 16 + cr;
#pragma unroll
        for (int ni = 0; ni < 8; ni++) {
            const int col = wn + ni * 8 + cc;
            const float b0 = brow[col], b1 = brow[col + 1];
            float* p0 = g_yp + (size_t)r0 * NCOLS + n0 + col;
            *(float2*)p0 = make_float2(acc[mi][ni][0] + b0, acc[mi][ni][1] + b1);
            float* p1 = p0 + (size_t)8 * NCOLS;
            *(float2*)p1 = make_float2(acc[mi][ni][2] + b0, acc[mi][ni][3] + b1);
        }
    }
}

// ---------------- 8. combine ----------------
__global__ void combine_k(float* __restrict__ out) {
    int idx = blockIdx.x * blockDim.x + threadIdx.x;
    if (idx >= NTOK * 256) return;
    int t = idx >> 8, j4 = idx & 255;
    int s0 = g_pair_slot[t * 2], s1 = g_pair_slot[t * 2 + 1];
    float w0 = g_top_w[t * 2], w1 = g_top_w[t * 2 + 1];
    float4 y0 = ((const float4*)g_yp)[(size_t)s0 * 256 + j4];
    float4 y1 = ((const float4*)g_yp)[(size_t)s1 * 256 + j4];
    float4 r;
    r.x = w0 * y0.x + w1 * y1.x;
    r.y = w0 * y0.y + w1 * y1.y;
    r.z = w0 * y0.z + w1 * y1.z;
    r.w = w0 * y0.w + w1 * y1.w;
    ((float4*)out)[idx] = r;
}

// ---------------- 9. aux loss ----------------
__global__ void aux_k(float* __restrict__ out, int out_size) {
    __shared__ float red[256];
    float local[NEXP];
#pragma unroll
    for (int e = 0; e < NEXP; e++) local[e] = 0.f;
    for (int t = threadIdx.x; t < NTOK; t += 256)
#pragma unroll
        for (int e = 0; e < NEXP; e++) local[e] += g_probs[t * NEXP + e];
    float aux = 0.f;
    for (int e = 0; e < NEXP; e++) {
        red[threadIdx.x] = local[e];
        __syncthreads();
        for (int s = 128; s; s >>= 1) {
            if (threadIdx.x < s) red[threadIdx.x] += red[threadIdx.x + s];
            __syncthreads();
        }
        if (threadIdx.x == 0)
            aux += ((float)g_counts[e] / (float)NTOK) * (red[0] / (float)NTOK);
        __syncthreads();
    }
    if (threadIdx.x == 0 && out_size > NTOK * D_IN)
        out[NTOK * D_IN] = (float)NEXP * aux;
}

// ---------------- launch (serial, single stream — R8 protocol) ----------
extern "C" void kernel_launch(void* const* d_in, const int* in_sizes, int n_in,
                              void* d_out, int out_size) {
    const float* x    = (const float*)d_in[0];
    const float* Wg   = (const float*)d_in[1];
    const float* fc1w = (const float*)d_in[2];
    const float* fc1b = (const float*)d_in[3];
    const float* fc2w = (const float*)d_in[4];
    const float* fc2b = (const float*)d_in[5];
    float* out = (float*)d_out;

    cudaFuncSetAttribute(gemm1_fused, cudaFuncAttributeMaxDynamicSharedMemorySize, SMEM_GEMM);
    cudaFuncSetAttribute(gemm2_mma,   cudaFuncAttributeMaxDynamicSharedMemorySize, SMEM_GEMM);

    init_k<<<(PMAX + 255) / 256, 256>>>();
    gate_k<<<NTOK / 8, 256>>>(x, Wg);
    off_k<<<1, 32>>>();
    scatter_k<<<(NTOK * 2 + 255) / 256, 256>>>();
    gatherx_k<<<PMAX, 256>>>(x);
    {
        size_t tot4 = (size_t)NEXP * H2 * D_IN / 4 + (size_t)NEXP * D_IN * HID / 4;
        conv_all<<<(unsigned)((tot4 + 255) / 256), 256>>>(fc1w, fc2w);
    }

    gemm1_fused<<<dim3(HID / 128, PMAX / TM), 256, SMEM_GEMM>>>(fc1b);
    gemm2_mma  <<<dim3(D_IN / 256, PMAX / TM), 256, SMEM_GEMM>>>(fc2b);

    combine_k<<<(NTOK * 256) / 256, 256>>>(out);
    aux_k<<<1, 256>>>(out, out_size);
}

// round 15
// speedup vs baseline: 3.3619x; 1.5616x over previous
#include <cuda_runtime.h>
#include <cuda_fp16.h>
#include <math.h>

typedef unsigned long long ull;

#define D_IN  1024
#define NEXP  8
#define HID   4096
#define H2    8192
#define NTOK  4096
#define PMAX  9216     // 8192 pairs + per-expert padding to 128

// GEMM tiling: 256 threads, K-chunk 64 (128B rows = SW128 atom)
#define TM    128
#define KC    64
#define A_TILE 16384          // 128 rows * 128B
#define B_TILE 32768          // 256 rows * 128B
#define STAGE  (A_TILE + B_TILE)       // A, B = 48KB
#define SMEM_GEMM (3 * STAGE)          // 144KB triple buffer

// ---------------- scratch (static device memory: allowed) ----------------
__device__ float g_yp[(size_t)PMAX * D_IN];   // per-pair expert out fp32
__device__ __half g_xh[(size_t)PMAX * D_IN];
__device__ __half g_ah[(size_t)PMAX * HID];
__device__ __half g_w1[(size_t)NEXP * H2 * D_IN];
__device__ __half g_w2[(size_t)NEXP * D_IN * HID];
__device__ float g_probs[NTOK * NEXP];
__device__ int   g_top_idx[NTOK * 2];
__device__ float g_top_w[NTOK * 2];
__device__ int   g_counts[NEXP];
__device__ int   g_cursor[NEXP];
__device__ int   g_off[NEXP + 1];
__device__ int   g_pair_token[PMAX];
__device__ int   g_pair_slot[NTOK * 2];

// ---------------- PTX helpers (baseline sm_80+, safe for sm_103 target) --
__device__ __forceinline__ unsigned smem_u32(const void* p) {
    unsigned a;
    asm("{ .reg .u64 t; cvta.to.shared.u64 t, %1; cvt.u32.u64 %0, t; }" : "=r"(a) : "l"(p));
    return a;
}
__device__ __forceinline__ void cpa16(unsigned dst, const void* src) {
    asm volatile("cp.async.cg.shared.global [%0], [%1], 16;" :: "r"(dst), "l"(src));
}
__device__ __forceinline__ void ldm4(unsigned* r, unsigned addr) {
    asm volatile("ldmatrix.sync.aligned.m8n8.x4.shared.b16 {%0,%1,%2,%3}, [%4];"
                 : "=r"(r[0]), "=r"(r[1]), "=r"(r[2]), "=r"(r[3]) : "r"(addr));
}
#define MMA(d, a, b) \
    asm volatile("mma.sync.aligned.m16n8k16.row.col.f32.f16.f16.f32 " \
        "{%0,%1,%2,%3}, {%4,%5,%6,%7}, {%8,%9}, {%0,%1,%2,%3};" \
        : "+f"((d)[0]), "+f"((d)[1]), "+f"((d)[2]), "+f"((d)[3]) \
        : "r"((a)[0]), "r"((a)[1]), "r"((a)[2]), "r"((a)[3]), "r"((b)[0]), "r"((b)[1]))

__device__ __forceinline__ unsigned sw128(unsigned bo) { return bo ^ ((bo >> 3) & 0x70); }
__device__ __forceinline__ float silu(float g) { return g / (1.f + expf(-g)); }

// ---------------- 1. init ----------------
__global__ void init_k() {
    int i = blockIdx.x * blockDim.x + threadIdx.x;
    if (i < NEXP) { g_counts[i] = 0; g_cursor[i] = 0; }
    if (i < PMAX) g_pair_token[i] = -1;
}

// ---------------- 2. gate (smem-cached Wg, conflict-free) ----------------
__global__ __launch_bounds__(256)
void gate_k(const float* __restrict__ x, const float* __restrict__ Wg) {
    __shared__ float Wt[NEXP][D_IN];     // 32KB, transposed
    const int tid = threadIdx.x;
    for (int i = tid; i < D_IN * NEXP; i += 256) {
        int d = i >> 3, e = i & 7;
        Wt[e][d] = Wg[i];
    }
    __syncthreads();
    const int wid = tid >> 5, lane = tid & 31;
    const int t = blockIdx.x * 8 + wid;           // 512 blocks * 8 warps = NTOK
    const float* xr = x + (size_t)t * D_IN;
    float acc[NEXP];
#pragma unroll
    for (int e = 0; e < NEXP; e++) acc[e] = 0.f;
    for (int d = lane; d < D_IN; d += 32) {
        float xv = xr[d];
#pragma unroll
        for (int e = 0; e < NEXP; e++) acc[e] = fmaf(xv, Wt[e][d], acc[e]);
    }
#pragma unroll
    for (int off = 16; off; off >>= 1)
#pragma unroll
        for (int e = 0; e < NEXP; e++)
            acc[e] += __shfl_down_sync(0xffffffffu, acc[e], off);
    if (lane == 0) {
        int e0 = 0; float v0 = acc[0];
#pragma unroll
        for (int e = 1; e < NEXP; e++) if (acc[e] > v0) { v0 = acc[e]; e0 = e; }
        int e1 = -1; float v1 = -1e30f;
#pragma unroll
        for (int e = 0; e < NEXP; e++) if (e != e0 && acc[e] > v1) { v1 = acc[e]; e1 = e; }
        float ew = expf(v1 - v0);
        float inv = 1.f / (1.f + ew);
        g_top_idx[t * 2]     = e0;
        g_top_idx[t * 2 + 1] = e1;
        g_top_w[t * 2]       = inv;
        g_top_w[t * 2 + 1]   = ew * inv;
        float p[NEXP], s = 0.f;
#pragma unroll
        for (int e = 0; e < NEXP; e++) { p[e] = expf(acc[e] - v0); s += p[e]; }
        float is = 1.f / s;
#pragma unroll
        for (int e = 0; e < NEXP; e++) g_probs[t * NEXP + e] = p[e] * is;
        atomicAdd(&g_counts[e0], 1);
        atomicAdd(&g_counts[e1], 1);
    }
}

// ---------------- 3. offsets ----------------
__global__ void off_k() {
    if (threadIdx.x == 0) {
        int o = 0;
#pragma unroll
        for (int e = 0; e < NEXP; e++) {
            g_off[e] = o;
            o += ((g_counts[e] + 127) >> 7) << 7;
        }
        g_off[NEXP] = o;
    }
}

// ---------------- 4. scatter ----------------
__global__ void scatter_k() {
    int i = blockIdx.x * blockDim.x + threadIdx.x;
    if (i >= NTOK * 2) return;
    int e = g_top_idx[i];
    int slot = g_off[e] + atomicAdd(&g_cursor[e], 1);
    g_pair_token[slot] = i >> 1;
    g_pair_slot[i] = slot;
}

// ---------------- 5a. gather x -> slot order, fp16 ----------------
__global__ void gatherx_k(const float* __restrict__ x) {
    int idx = blockIdx.x * blockDim.x + threadIdx.x;    // PMAX * 256 float4
    int slot = idx >> 8;
    if (slot >= PMAX) return;
    int j = idx & 255;
    int tok = g_pair_token[slot];
    float4 v = make_float4(0.f, 0.f, 0.f, 0.f);
    if (tok >= 0) v = ((const float4*)x)[(size_t)tok * 256 + j];
    size_t o = (size_t)slot * 512 + j * 2;
    ((__half2*)g_xh)[o]     = __floats2half2_rn(v.x, v.y);
    ((__half2*)g_xh)[o + 1] = __floats2half2_rn(v.z, v.w);
}

// ---------------- 5b. weight conversion fp32 -> fp16 ----------
__global__ void conv_all(const float* __restrict__ w1, const float* __restrict__ w2) {
    const size_t N1 = (size_t)NEXP * H2 * D_IN / 4;
    size_t i = (size_t)blockIdx.x * blockDim.x + threadIdx.x;
    if (i < N1) {
        float4 v = ((const float4*)w1)[i];
        ((__half2*)g_w1)[i * 2]     = __floats2half2_rn(v.x, v.y);
        ((__half2*)g_w1)[i * 2 + 1] = __floats2half2_rn(v.z, v.w);
    } else {
        size_t j = i - N1;
        if (j >= (size_t)NEXP * D_IN * HID / 4) return;
        float4 v = ((const float4*)w2)[j];
        ((__half2*)g_w2)[j * 2]     = __floats2half2_rn(v.x, v.y);
        ((__half2*)g_w2)[j * 2 + 1] = __floats2half2_rn(v.z, v.w);
    }
}

// ---------------- stage loaders: gmem fp16 -> SW128 SMEM via cp.async ----
__device__ __forceinline__ void stageA(unsigned smDst, const __half* g, int stride, int tid) {
#pragma unroll
    for (int i = 0; i < 4; i++) {               // 128 rows * 8 segs = 1024
        int idx = (i << 8) | tid;
        int r = idx >> 3, s = idx & 7;
        unsigned bo = (unsigned)((r << 7) | (s << 4));
        cpa16(smDst + sw128(bo), g + (size_t)r * stride + (s << 3));
    }
}
__device__ __forceinline__ void stageB(unsigned smDst, const __half* g, int stride, int tid) {
#pragma unroll
    for (int i = 0; i < 8; i++) {               // 256 rows * 8 segs = 2048
        int idx = (i << 8) | tid;
        int r = idx >> 3, s = idx & 7;
        unsigned bo = (unsigned)((r << 7) | (s << 4));
        cpa16(smDst + sw128(bo), g + (size_t)r * stride + (s << 3));
    }
}

// ---------------- 6. GEMM1 (fc1) fused with SiLU*val, fp16 single -------
// Per CTA: 128 rows x 128 act cols. B smem rows: [gate 0..127 ; val 128..255].
// 3-stage cp.async pipeline.
__global__ __launch_bounds__(256, 1)
void gemm1_fused(const float* __restrict__ bias) {
    extern __shared__ char smem[];
    const int rows_total = g_off[NEXP];
    const int row0 = blockIdx.y * TM;
    const int n0   = blockIdx.x * 128;          // act col base (0..4095)
    if (row0 >= rows_total) return;

    int e = 0;
#pragma unroll
    for (int i = 0; i < NEXP; i++) if (g_off[i + 1] <= row0) e = i + 1;

    const __half* A = g_xh + (size_t)row0 * D_IN;
    const size_t wbase = (size_t)e * H2 * D_IN + (size_t)n0 * D_IN;
    const __half* Bg = g_w1 + wbase;
    const __half* Bv = g_w1 + wbase + (size_t)HID * D_IN;

    const int tid = threadIdx.x;
    const int lane = tid & 31, wid = tid >> 5;
    const int wm = (wid & 1) * 64;        // 2 warps in M
    const int wn = (wid >> 1) * 32;       // 4 warps in N
    const unsigned sb = smem_u32(smem);

    const unsigned aRow = wm + (lane & 15);
    const unsigned aKb  = (unsigned)(lane >> 4) << 4;
    const unsigned bRow = wn + (lane & 7) + ((unsigned)(lane >> 4) << 3);
    const unsigned bKb  = (unsigned)((lane >> 3) & 1) << 4;

    float accg[4][4][4], accv[4][4][4];
#pragma unroll
    for (int mi = 0; mi < 4; mi++)
#pragma unroll
        for (int ni = 0; ni < 4; ni++)
#pragma unroll
            for (int j = 0; j < 4; j++) { accg[mi][ni][j] = 0.f; accv[mi][ni][j] = 0.f; }

    const int T = D_IN / KC;   // 16

    // prologue: stage chunks 0,1 into buffers 0,1
#pragma unroll
    for (int p = 0; p < 2; p++) {
        unsigned s0 = sb + p * STAGE;
        const int kOff = p * KC;
        stageA(s0,                  A  + kOff, D_IN, tid);
        stageA(s0 + A_TILE,         Bg + kOff, D_IN, tid);
        stageA(s0 + A_TILE + 16384, Bv + kOff, D_IN, tid);
        asm volatile("cp.async.commit_group;" ::: "memory");
    }

    int buf = 0;
    for (int kt = 0; kt < T; kt++) {
        if (kt + 1 < T) { asm volatile("cp.async.wait_group 1;" ::: "memory"); }
        else            { asm volatile("cp.async.wait_group 0;" ::: "memory"); }
        __syncthreads();                 // chunk kt ready; all reads of stage-target done
        if (kt + 2 < T) {
            const int kOff = (kt + 2) * KC;
            int nb = buf + 2; if (nb >= 3) nb -= 3;
            unsigned s1 = sb + nb * STAGE;
            stageA(s1,                  A  + kOff, D_IN, tid);
            stageA(s1 + A_TILE,         Bg + kOff, D_IN, tid);
            stageA(s1 + A_TILE + 16384, Bv + kOff, D_IN, tid);
            asm volatile("cp.async.commit_group;" ::: "memory");
        }

        const unsigned sA = sb + buf * STAGE;
        const unsigned sB = sA + A_TILE;     // 256 rows: gate then val

#pragma unroll
        for (int ks = 0; ks < 4; ks++) {
            const unsigned kb = ks * 32;
            unsigned ra[4][4], rg[2][4], rv[2][4];
#pragma unroll
            for (int mi = 0; mi < 4; mi++)
                ldm4(ra[mi], sA + sw128((aRow + mi * 16) * 128 + kb + aKb));
#pragma unroll
            for (int g = 0; g < 2; g++) {
                ldm4(rg[g], sB + sw128((bRow + g * 16) * 128 + kb + bKb));
                ldm4(rv[g], sB + sw128((128 + bRow + g * 16) * 128 + kb + bKb));
            }
#pragma unroll
            for (int mi = 0; mi < 4; mi++)
#pragma unroll
                for (int ni = 0; ni < 4; ni++) {
                    MMA(accg[mi][ni], ra[mi], &rg[ni >> 1][(ni & 1) * 2]);
                    MMA(accv[mi][ni], ra[mi], &rv[ni >> 1][(ni & 1) * 2]);
                }
        }
        if (++buf == 3) buf = 0;
    }

    // epilogue: silu(g+bg)*(v+bv) -> fp16 -> g_ah
    const float* bg = bias + (size_t)e * H2 + n0;
    const float* bvp = bg + HID;
    const int cr = lane >> 2;
    const int cc = (lane & 3) * 2;
#pragma unroll
    for (int mi = 0; mi < 4; mi++) {
        const int r0 = row0 + wm + mi * 16 + cr;
#pragma unroll
        for (int ni = 0; ni < 4; ni++) {
            const int col = wn + ni * 8 + cc;
            const float bg0 = bg[col], bg1 = bg[col + 1];
            const float bv0 = bvp[col], bv1 = bvp[col + 1];
            const size_t gc = (size_t)(n0 + col);
            {
                float a0 = silu(accg[mi][ni][0] + bg0) * (accv[mi][ni][0] + bv0);
                float a1 = silu(accg[mi][ni][1] + bg1) * (accv[mi][ni][1] + bv1);
                *(__half2*)(g_ah + (size_t)r0 * HID + gc) = __floats2half2_rn(a0, a1);
            }
            {
                float a0 = silu(accg[mi][ni][2] + bg0) * (accv[mi][ni][2] + bv0);
                float a1 = silu(accg[mi][ni][3] + bg1) * (accv[mi][ni][3] + bv1);
                *(__half2*)(g_ah + (size_t)(r0 + 8) * HID + gc) = __floats2half2_rn(a0, a1);
            }
        }
    }
}

// ---------------- 7. GEMM2 (fc2): 128x256 tile, fp16 single -------------
__global__ __launch_bounds__(256, 1)
void gemm2_mma(const float* __restrict__ bias) {
    extern __shared__ char smem[];
    const int KDIM = HID, NCOLS = D_IN;
    const int rows_total = g_off[NEXP];
    const int row0 = blockIdx.y * TM;
    const int n0   = blockIdx.x * 256;
    if (row0 >= rows_total) return;

    int e = 0;
#pragma unroll
    for (int i = 0; i < NEXP; i++) if (g_off[i + 1] <= row0) e = i + 1;

    const __half* A = g_ah + (size_t)row0 * KDIM;
    const __half* B = g_w2 + (size_t)e * NCOLS * KDIM + (size_t)n0 * KDIM;

    const int tid = threadIdx.x;
    const int lane = tid & 31, wid = tid >> 5;
    const int wm = (wid & 1) * 64;
    const int wn = (wid >> 1) * 64;
    const unsigned sb = smem_u32(smem);

    const unsigned aRow = wm + (lane & 15);
    const unsigned aKb  = (unsigned)(lane >> 4) << 4;
    const unsigned bRow = wn + (lane & 7) + ((unsigned)(lane >> 4) << 3);
    const unsigned bKb  = (unsigned)((lane >> 3) & 1) << 4;

    float acc[4][8][4];
#pragma unroll
    for (int mi = 0; mi < 4; mi++)
#pragma unroll
        for (int ni = 0; ni < 8; ni++)
#pragma unroll
            for (int j = 0; j < 4; j++) acc[mi][ni][j] = 0.f;

    const int T = KDIM / KC;   // 64

#pragma unroll
    for (int p = 0; p < 2; p++) {
        unsigned s0 = sb + p * STAGE;
        const int kOff = p * KC;
        stageA(s0,          A + kOff, KDIM, tid);
        stageB(s0 + A_TILE, B + kOff, KDIM, tid);
        asm volatile("cp.async.commit_group;" ::: "memory");
    }

    int buf = 0;
    for (int kt = 0; kt < T; kt++) {
        if (kt + 1 < T) { asm volatile("cp.async.wait_group 1;" ::: "memory"); }
        else            { asm volatile("cp.async.wait_group 0;" ::: "memory"); }
        __syncthreads();
        if (kt + 2 < T) {
            const int kOff = (kt + 2) * KC;
            int nb = buf + 2; if (nb >= 3) nb -= 3;
            unsigned s1 = sb + nb * STAGE;
            stageA(s1,          A + kOff, KDIM, tid);
            stageB(s1 + A_TILE, B + kOff, KDIM, tid);
            asm volatile("cp.async.commit_group;" ::: "memory");
        }

        const unsigned sA = sb + buf * STAGE;
        const unsigned sB = sA + A_TILE;

#pragma unroll
        for (int ks = 0; ks < 4; ks++) {
            const unsigned kb = ks * 32;
            unsigned ra[4][4], rb[4][4];
#pragma unroll
            for (int mi = 0; mi < 4; mi++)
                ldm4(ra[mi], sA + sw128((aRow + mi * 16) * 128 + kb + aKb));
#pragma unroll
            for (int g = 0; g < 4; g++)
                ldm4(rb[g], sB + sw128((bRow + g * 16) * 128 + kb + bKb));
#pragma unroll
            for (int mi = 0; mi < 4; mi++)
#pragma unroll
                for (int ni = 0; ni < 8; ni++)
                    MMA(acc[mi][ni], ra[mi], &rb[ni >> 1][(ni & 1) * 2]);
        }
        if (++buf == 3) buf = 0;
    }

    const float* brow = bias + (size_t)e * NCOLS + n0;
    const int cr = lane >> 2;
    const int cc = (lane & 3) * 2;
#pragma unroll
    for (int mi = 0; mi < 4; mi++) {
        const int r0 = row0 + wm + mi * 16 + cr;
#pragma unroll
        for (int ni = 0; ni < 8; ni++) {
            const int col = wn + ni * 8 + cc;
            const float b0 = brow[col], b1 = brow[col + 1];
            float* p0 = g_yp + (size_t)r0 * NCOLS + n0 + col;
            *(float2*)p0 = make_float2(acc[mi][ni][0] + b0, acc[mi][ni][1] + b1);
            float* p1 = p0 + (size_t)8 * NCOLS;
            *(float2*)p1 = make_float2(acc[mi][ni][2] + b0, acc[mi][ni][3] + b1);
        }
    }
}

// ---------------- 8. combine ----------------
__global__ void combine_k(float* __restrict__ out) {
    int idx = blockIdx.x * blockDim.x + threadIdx.x;
    if (idx >= NTOK * 256) return;
    int t = idx >> 8, j4 = idx & 255;
    int s0 = g_pair_slot[t * 2], s1 = g_pair_slot[t * 2 + 1];
    float w0 = g_top_w[t * 2], w1 = g_top_w[t * 2 + 1];
    float4 y0 = ((const float4*)g_yp)[(size_t)s0 * 256 + j4];
    float4 y1 = ((const float4*)g_yp)[(size_t)s1 * 256 + j4];
    float4 r;
    r.x = w0 * y0.x + w1 * y1.x;
    r.y = w0 * y0.y + w1 * y1.y;
    r.z = w0 * y0.z + w1 * y1.z;
    r.w = w0 * y0.w + w1 * y1.w;
    ((float4*)out)[idx] = r;
}

// ---------------- 9. aux loss ----------------
__global__ void aux_k(float* __restrict__ out, int out_size) {
    __shared__ float red[256];
    float local[NEXP];
#pragma unroll
    for (int e = 0; e < NEXP; e++) local[e] = 0.f;
    for (int t = threadIdx.x; t < NTOK; t += 256)
#pragma unroll
        for (int e = 0; e < NEXP; e++) local[e] += g_probs[t * NEXP + e];
    float aux = 0.f;
    for (int e = 0; e < NEXP; e++) {
        red[threadIdx.x] = local[e];
        __syncthreads();
        for (int s = 128; s; s >>= 1) {
            if (threadIdx.x < s) red[threadIdx.x] += red[threadIdx.x + s];
            __syncthreads();
        }
        if (threadIdx.x == 0)
            aux += ((float)g_counts[e] / (float)NTOK) * (red[0] / (float)NTOK);
        __syncthreads();
    }
    if (threadIdx.x == 0 && out_size > NTOK * D_IN)
        out[NTOK * D_IN] = (float)NEXP * aux;
}

// ---------------- launch (serial, single stream — R8 protocol) ----------
extern "C" void kernel_launch(void* const* d_in, const int* in_sizes, int n_in,
                              void* d_out, int out_size) {
    const float* x    = (const float*)d_in[0];
    const float* Wg   = (const float*)d_in[1];
    const float* fc1w = (const float*)d_in[2];
    const float* fc1b = (const float*)d_in[3];
    const float* fc2w = (const float*)d_in[4];
    const float* fc2b = (const float*)d_in[5];
    float* out = (float*)d_out;

    cudaFuncSetAttribute(gemm1_fused, cudaFuncAttributeMaxDynamicSharedMemorySize, SMEM_GEMM);
    cudaFuncSetAttribute(gemm2_mma,   cudaFuncAttributeMaxDynamicSharedMemorySize, SMEM_GEMM);

    init_k<<<(PMAX + 255) / 256, 256>>>();
    gate_k<<<NTOK / 8, 256>>>(x, Wg);
    off_k<<<1, 32>>>();
    scatter_k<<<(NTOK * 2 + 255) / 256, 256>>>();
    gatherx_k<<<PMAX, 256>>>(x);
    {
        size_t tot4 = (size_t)NEXP * H2 * D_IN / 4 + (size_t)NEXP * D_IN * HID / 4;
        conv_all<<<(unsigned)((tot4 + 255) / 256), 256>>>(fc1w, fc2w);
    }

    gemm1_fused<<<dim3(HID / 128, PMAX / TM), 256, SMEM_GEMM>>>(fc1b);
    gemm2_mma  <<<dim3(D_IN / 256, PMAX / TM), 256, SMEM_GEMM>>>(fc2b);

    combine_k<<<(NTOK * 256) / 256, 256>>>(out);
    aux_k<<<1, 256>>>(out, out_size);
}

// round 16
// speedup vs baseline: 3.4103x; 1.0144x over previous
#include <cuda_runtime.h>
#include <cuda_fp16.h>
#include <math.h>

typedef unsigned long long ull;

#define D_IN  1024
#define NEXP  8
#define HID   4096
#define H2    8192
#define NTOK  4096
#define PMAX  9216     // 8192 pairs + per-expert padding to 128

// GEMM tiling: 256 threads, staged K-block 128 = 2 x 64-k sub-tiles (SW128)
#define TM    128
#define KC    128
#define A_TILE 16384          // 128 rows * 128B  (one 64-k sub-tile)
#define B_TILE 32768          // 256 rows * 128B  (one 64-k sub-tile)
#define BUF   (2*A_TILE + 2*B_TILE)    // 96KB: A0,A1,B0,B1
#define SMEM_GEMM (2 * BUF)            // 192KB double buffer

// ---------------- scratch (static device memory: allowed) ----------------
__device__ __half g_xh[(size_t)PMAX * D_IN];
__device__ __half g_ah[(size_t)PMAX * HID];
__device__ __half g_w1[(size_t)NEXP * H2 * D_IN];
__device__ __half g_w2[(size_t)NEXP * D_IN * HID];
__device__ float g_probs[NTOK * NEXP];
__device__ int   g_top_idx[NTOK * 2];
__device__ float g_top_w[NTOK * 2];
__device__ int   g_counts[NEXP];
__device__ int   g_cursor[NEXP];
__device__ int   g_off[NEXP + 1];
__device__ int   g_pair_token[PMAX];
__device__ float g_pair_w[PMAX];

// ---------------- PTX helpers (baseline sm_80+, safe for sm_103 target) --
__device__ __forceinline__ unsigned smem_u32(const void* p) {
    unsigned a;
    asm("{ .reg .u64 t; cvta.to.shared.u64 t, %1; cvt.u32.u64 %0, t; }" : "=r"(a) : "l"(p));
    return a;
}
__device__ __forceinline__ void cpa16(unsigned dst, const void* src) {
    asm volatile("cp.async.cg.shared.global [%0], [%1], 16;" :: "r"(dst), "l"(src));
}
__device__ __forceinline__ void ldm4(unsigned* r, unsigned addr) {
    asm volatile("ldmatrix.sync.aligned.m8n8.x4.shared.b16 {%0,%1,%2,%3}, [%4];"
                 : "=r"(r[0]), "=r"(r[1]), "=r"(r[2]), "=r"(r[3]) : "r"(addr));
}
#define MMA(d, a, b) \
    asm volatile("mma.sync.aligned.m16n8k16.row.col.f32.f16.f16.f32 " \
        "{%0,%1,%2,%3}, {%4,%5,%6,%7}, {%8,%9}, {%0,%1,%2,%3};" \
        : "+f"((d)[0]), "+f"((d)[1]), "+f"((d)[2]), "+f"((d)[3]) \
        : "r"((a)[0]), "r"((a)[1]), "r"((a)[2]), "r"((a)[3]), "r"((b)[0]), "r"((b)[1]))

__device__ __forceinline__ unsigned sw128(unsigned bo) { return bo ^ ((bo >> 3) & 0x70); }
__device__ __forceinline__ float silu(float g) { return g / (1.f + expf(-g)); }

// ---------------- 1. init / zero-out ----------------
__global__ void init_k() {
    int i = blockIdx.x * blockDim.x + threadIdx.x;
    if (i < NEXP) { g_counts[i] = 0; g_cursor[i] = 0; }
    if (i < PMAX) g_pair_token[i] = -1;
}
__global__ void zero_out_k(float* __restrict__ out, int n) {
    int i = blockIdx.x * blockDim.x + threadIdx.x;
    if (i < n) out[i] = 0.f;
}

// ---------------- 2. gate (smem-cached Wg, conflict-free) ----------------
__global__ __launch_bounds__(256)
void gate_k(const float* __restrict__ x, const float* __restrict__ Wg) {
    __shared__ float Wt[NEXP][D_IN];     // 32KB, transposed
    const int tid = threadIdx.x;
    for (int i = tid; i < D_IN * NEXP; i += 256) {
        int d = i >> 3, e = i & 7;
        Wt[e][d] = Wg[i];
    }
    __syncthreads();
    const int wid = tid >> 5, lane = tid & 31;
    const int t = blockIdx.x * 8 + wid;
    const float* xr = x + (size_t)t * D_IN;
    float acc[NEXP];
#pragma unroll
    for (int e = 0; e < NEXP; e++) acc[e] = 0.f;
    for (int d = lane; d < D_IN; d += 32) {
        float xv = xr[d];
#pragma unroll
        for (int e = 0; e < NEXP; e++) acc[e] = fmaf(xv, Wt[e][d], acc[e]);
    }
#pragma unroll
    for (int off = 16; off; off >>= 1)
#pragma unroll
        for (int e = 0; e < NEXP; e++)
            acc[e] += __shfl_down_sync(0xffffffffu, acc[e], off);
    if (lane == 0) {
        int e0 = 0; float v0 = acc[0];
#pragma unroll
        for (int e = 1; e < NEXP; e++) if (acc[e] > v0) { v0 = acc[e]; e0 = e; }
        int e1 = -1; float v1 = -1e30f;
#pragma unroll
        for (int e = 0; e < NEXP; e++) if (e != e0 && acc[e] > v1) { v1 = acc[e]; e1 = e; }
        float ew = expf(v1 - v0);
        float inv = 1.f / (1.f + ew);
        g_top_idx[t * 2]     = e0;
        g_top_idx[t * 2 + 1] = e1;
        g_top_w[t * 2]       = inv;
        g_top_w[t * 2 + 1]   = ew * inv;
        float p[NEXP], s = 0.f;
#pragma unroll
        for (int e = 0; e < NEXP; e++) { p[e] = expf(acc[e] - v0); s += p[e]; }
        float is = 1.f / s;
#pragma unroll
        for (int e = 0; e < NEXP; e++) g_probs[t * NEXP + e] = p[e] * is;
        atomicAdd(&g_counts[e0], 1);
        atomicAdd(&g_counts[e1], 1);
    }
}

// ---------------- 3. offsets ----------------
__global__ void off_k() {
    if (threadIdx.x == 0) {
        int o = 0;
#pragma unroll
        for (int e = 0; e < NEXP; e++) {
            g_off[e] = o;
            o += ((g_counts[e] + 127) >> 7) << 7;
        }
        g_off[NEXP] = o;
    }
}

// ---------------- 4. scatter (records slot -> token, weight) ------------
__global__ void scatter_k() {
    int i = blockIdx.x * blockDim.x + threadIdx.x;
    if (i >= NTOK * 2) return;
    int e = g_top_idx[i];
    int slot = g_off[e] + atomicAdd(&g_cursor[e], 1);
    g_pair_token[slot] = i >> 1;
    g_pair_w[slot] = g_top_w[i];
}

// ---------------- 5a. gather x -> slot order, fp16 ----------------
__global__ void gatherx_k(const float* __restrict__ x) {
    int idx = blockIdx.x * blockDim.x + threadIdx.x;    // PMAX * 256 float4
    int slot = idx >> 8;
    if (slot >= PMAX) return;
    int j = idx & 255;
    int tok = g_pair_token[slot];
    float4 v = make_float4(0.f, 0.f, 0.f, 0.f);
    if (tok >= 0) v = ((const float4*)x)[(size_t)tok * 256 + j];
    size_t o = (size_t)slot * 512 + j * 2;
    ((__half2*)g_xh)[o]     = __floats2half2_rn(v.x, v.y);
    ((__half2*)g_xh)[o + 1] = __floats2half2_rn(v.z, v.w);
}

// ---------------- 5b. weight conversion fp32 -> fp16 ----------
__global__ void conv_all(const float* __restrict__ w1, const float* __restrict__ w2) {
    const size_t N1 = (size_t)NEXP * H2 * D_IN / 4;
    size_t i = (size_t)blockIdx.x * blockDim.x + threadIdx.x;
    if (i < N1) {
        float4 v = ((const float4*)w1)[i];
        ((__half2*)g_w1)[i * 2]     = __floats2half2_rn(v.x, v.y);
        ((__half2*)g_w1)[i * 2 + 1] = __floats2half2_rn(v.z, v.w);
    } else {
        size_t j = i - N1;
        if (j >= (size_t)NEXP * D_IN * HID / 4) return;
        float4 v = ((const float4*)w2)[j];
        ((__half2*)g_w2)[j * 2]     = __floats2half2_rn(v.x, v.y);
        ((__half2*)g_w2)[j * 2 + 1] = __floats2half2_rn(v.z, v.w);
    }
}

// ---------------- stage loaders: gmem fp16 -> SW128 SMEM via cp.async ----
__device__ __forceinline__ void stageA(unsigned smDst, const __half* g, int stride, int tid) {
#pragma unroll
    for (int i = 0; i < 4; i++) {               // 128 rows * 8 segs = 1024
        int idx = (i << 8) | tid;
        int r = idx >> 3, s = idx & 7;
        unsigned bo = (unsigned)((r << 7) | (s << 4));
        cpa16(smDst + sw128(bo), g + (size_t)r * stride + (s << 3));
    }
}
__device__ __forceinline__ void stageB(unsigned smDst, const __half* g, int stride, int tid) {
#pragma unroll
    for (int i = 0; i < 8; i++) {               // 256 rows * 8 segs = 2048
        int idx = (i << 8) | tid;
        int r = idx >> 3, s = idx & 7;
        unsigned bo = (unsigned)((r << 7) | (s << 4));
        cpa16(smDst + sw128(bo), g + (size_t)r * stride + (s << 3));
    }
}

// ---------------- 6. GEMM1 (fc1) fused with SiLU*val, fp16 single -------
// Buffer: [A0 16K][A1 16K][B0 32K][B1 32K]; sub-tiles are 64-k each.
__global__ __launch_bounds__(256, 1)
void gemm1_fused(const float* __restrict__ bias) {
    extern __shared__ char smem[];
    const int rows_total = g_off[NEXP];
    const int row0 = blockIdx.y * TM;
    const int n0   = blockIdx.x * 128;          // act col base (0..4095)
    if (row0 >= rows_total) return;

    int e = 0;
#pragma unroll
    for (int i = 0; i < NEXP; i++) if (g_off[i + 1] <= row0) e = i + 1;

    const __half* A = g_xh + (size_t)row0 * D_IN;
    const size_t wbase = (size_t)e * H2 * D_IN + (size_t)n0 * D_IN;
    const __half* Bg = g_w1 + wbase;
    const __half* Bv = g_w1 + wbase + (size_t)HID * D_IN;

    const int tid = threadIdx.x;
    const int lane = tid & 31, wid = tid >> 5;
    const int wm = (wid & 1) * 64;        // 2 warps in M
    const int wn = (wid >> 1) * 32;       // 4 warps in N
    const unsigned sb = smem_u32(smem);

    const unsigned aRow = wm + (lane & 15);
    const unsigned aKb  = (unsigned)(lane >> 4) << 4;
    const unsigned bRow = wn + (lane & 7) + ((unsigned)(lane >> 4) << 3);
    const unsigned bKb  = (unsigned)((lane >> 3) & 1) << 4;

    float accg[4][4][4], accv[4][4][4];
#pragma unroll
    for (int mi = 0; mi < 4; mi++)
#pragma unroll
        for (int ni = 0; ni < 4; ni++)
#pragma unroll
            for (int j = 0; j < 4; j++) { accg[mi][ni][j] = 0.f; accv[mi][ni][j] = 0.f; }

    const int T = D_IN / KC;   // 8

    // prologue: stage block 0 (sub-tiles k=0,64) into buffer 0
    {
        unsigned s0 = sb;
        stageA(s0,                       A,       D_IN, tid);
        stageA(s0 + A_TILE,              A + 64,  D_IN, tid);
        stageA(s0 + 2*A_TILE,            Bg,      D_IN, tid);
        stageA(s0 + 2*A_TILE + 16384,    Bv,      D_IN, tid);
        stageA(s0 + 2*A_TILE + B_TILE,           Bg + 64, D_IN, tid);
        stageA(s0 + 2*A_TILE + B_TILE + 16384,   Bv + 64, D_IN, tid);
        asm volatile("cp.async.commit_group;" ::: "memory");
    }

    for (int kt = 0; kt < T; kt++) {
        const int buf = kt & 1;
        asm volatile("cp.async.wait_group 0;" ::: "memory");
        __syncthreads();
        if (kt + 1 < T) {
            const int kOff = (kt + 1) * KC;
            unsigned s1 = sb + (buf ^ 1) * BUF;
            stageA(s1,                       A + kOff,       D_IN, tid);
            stageA(s1 + A_TILE,              A + kOff + 64,  D_IN, tid);
            stageA(s1 + 2*A_TILE,            Bg + kOff,      D_IN, tid);
            stageA(s1 + 2*A_TILE + 16384,    Bv + kOff,      D_IN, tid);
            stageA(s1 + 2*A_TILE + B_TILE,           Bg + kOff + 64, D_IN, tid);
            stageA(s1 + 2*A_TILE + B_TILE + 16384,   Bv + kOff + 64, D_IN, tid);
            asm volatile("cp.async.commit_group;" ::: "memory");
        }

        const unsigned base = sb + buf * BUF;
#pragma unroll
        for (int h = 0; h < 2; h++) {
            const unsigned sA = base + h * A_TILE;
            const unsigned sB = base + 2 * A_TILE + h * B_TILE;
#pragma unroll
            for (int ks = 0; ks < 4; ks++) {
                const unsigned kb = ks * 32;
                unsigned ra[4][4], rg[2][4], rv[2][4];
#pragma unroll
                for (int mi = 0; mi < 4; mi++)
                    ldm4(ra[mi], sA + sw128((aRow + mi * 16) * 128 + kb + aKb));
#pragma unroll
                for (int g = 0; g < 2; g++) {
                    ldm4(rg[g], sB + sw128((bRow + g * 16) * 128 + kb + bKb));
                    ldm4(rv[g], sB + sw128((128 + bRow + g * 16) * 128 + kb + bKb));
                }
#pragma unroll
                for (int mi = 0; mi < 4; mi++)
#pragma unroll
                    for (int ni = 0; ni < 4; ni++) {
                        MMA(accg[mi][ni], ra[mi], &rg[ni >> 1][(ni & 1) * 2]);
                        MMA(accv[mi][ni], ra[mi], &rv[ni >> 1][(ni & 1) * 2]);
                    }
            }
        }
    }

    // epilogue: silu(g+bg)*(v+bv) -> fp16 -> g_ah
    const float* bg = bias + (size_t)e * H2 + n0;
    const float* bvp = bg + HID;
    const int cr = lane >> 2;
    const int cc = (lane & 3) * 2;
#pragma unroll
    for (int mi = 0; mi < 4; mi++) {
        const int r0 = row0 + wm + mi * 16 + cr;
#pragma unroll
        for (int ni = 0; ni < 4; ni++) {
            const int col = wn + ni * 8 + cc;
            const float bg0 = bg[col], bg1 = bg[col + 1];
            const float bv0 = bvp[col], bv1 = bvp[col + 1];
            const size_t gc = (size_t)(n0 + col);
            {
                float a0 = silu(accg[mi][ni][0] + bg0) * (accv[mi][ni][0] + bv0);
                float a1 = silu(accg[mi][ni][1] + bg1) * (accv[mi][ni][1] + bv1);
                *(__half2*)(g_ah + (size_t)r0 * HID + gc) = __floats2half2_rn(a0, a1);
            }
            {
                float a0 = silu(accg[mi][ni][2] + bg0) * (accv[mi][ni][2] + bv0);
                float a1 = silu(accg[mi][ni][3] + bg1) * (accv[mi][ni][3] + bv1);
                *(__half2*)(g_ah + (size_t)(r0 + 8) * HID + gc) = __floats2half2_rn(a0, a1);
            }
        }
    }
}

// ---------------- 7. GEMM2 (fc2): 128x256 tile + fused weighted combine -
// Epilogue: out[token] += w_slot * (acc + bias)  (2 fp32 adds per element,
// fp32 add is commutative -> bit-deterministic regardless of order)
__global__ __launch_bounds__(256, 1)
void gemm2_mma(const float* __restrict__ bias, float* __restrict__ out) {
    extern __shared__ char smem[];
    const int KDIM = HID, NCOLS = D_IN;
    const int rows_total = g_off[NEXP];
    const int row0 = blockIdx.y * TM;
    const int n0   = blockIdx.x * 256;
    if (row0 >= rows_total) return;

    int e = 0;
#pragma unroll
    for (int i = 0; i < NEXP; i++) if (g_off[i + 1] <= row0) e = i + 1;

    const __half* A = g_ah + (size_t)row0 * KDIM;
    const __half* B = g_w2 + (size_t)e * NCOLS * KDIM + (size_t)n0 * KDIM;

    const int tid = threadIdx.x;
    const int lane = tid & 31, wid = tid >> 5;
    const int wm = (wid & 1) * 64;
    const int wn = (wid >> 1) * 64;
    const unsigned sb = smem_u32(smem);

    const unsigned aRow = wm + (lane & 15);
    const unsigned aKb  = (unsigned)(lane >> 4) << 4;
    const unsigned bRow = wn + (lane & 7) + ((unsigned)(lane >> 4) << 3);
    const unsigned bKb  = (unsigned)((lane >> 3) & 1) << 4;

    float acc[4][8][4];
#pragma unroll
    for (int mi = 0; mi < 4; mi++)
#pragma unroll
        for (int ni = 0; ni < 8; ni++)
#pragma unroll
            for (int j = 0; j < 4; j++) acc[mi][ni][j] = 0.f;

    const int T = KDIM / KC;   // 32

    {
        unsigned s0 = sb;
        stageA(s0,                      A,      KDIM, tid);
        stageA(s0 + A_TILE,             A + 64, KDIM, tid);
        stageB(s0 + 2 * A_TILE,         B,      KDIM, tid);
        stageB(s0 + 2 * A_TILE + B_TILE, B + 64, KDIM, tid);
        asm volatile("cp.async.commit_group;" ::: "memory");
    }

    for (int kt = 0; kt < T; kt++) {
        const int buf = kt & 1;
        asm volatile("cp.async.wait_group 0;" ::: "memory");
        __syncthreads();
        if (kt + 1 < T) {
            const int kOff = (kt + 1) * KC;
            unsigned s1 = sb + (buf ^ 1) * BUF;
            stageA(s1,                      A + kOff,      KDIM, tid);
            stageA(s1 + A_TILE,             A + kOff + 64, KDIM, tid);
            stageB(s1 + 2 * A_TILE,         B + kOff,      KDIM, tid);
            stageB(s1 + 2 * A_TILE + B_TILE, B + kOff + 64, KDIM, tid);
            asm volatile("cp.async.commit_group;" ::: "memory");
        }

        const unsigned base = sb + buf * BUF;
#pragma unroll
        for (int h = 0; h < 2; h++) {
            const unsigned sA = base + h * A_TILE;
            const unsigned sB = base + 2 * A_TILE + h * B_TILE;
#pragma unroll
            for (int ks = 0; ks < 4; ks++) {
                const unsigned kb = ks * 32;
                unsigned ra[4][4], rb[4][4];
#pragma unroll
                for (int mi = 0; mi < 4; mi++)
                    ldm4(ra[mi], sA + sw128((aRow + mi * 16) * 128 + kb + aKb));
#pragma unroll
                for (int g = 0; g < 4; g++)
                    ldm4(rb[g], sB + sw128((bRow + g * 16) * 128 + kb + bKb));
#pragma unroll
                for (int mi = 0; mi < 4; mi++)
#pragma unroll
                    for (int ni = 0; ni < 8; ni++)
                        MMA(acc[mi][ni], ra[mi], &rb[ni >> 1][(ni & 1) * 2]);
            }
        }
    }

    // epilogue: weighted atomic combine into out
    const float* brow = bias + (size_t)e * NCOLS + n0;
    const int cr = lane >> 2;
    const int cc = (lane & 3) * 2;
#pragma unroll
    for (int mi = 0; mi < 4; mi++) {
        const int r0 = row0 + wm + mi * 16 + cr;      // global slot (row r0)
        const int r1 = r0 + 8;
        const int tok0 = g_pair_token[r0];
        const int tok1 = g_pair_token[r1];
        const float w0 = g_pair_w[r0];
        const float w1 = g_pair_w[r1];
        float* o0 = out + (size_t)tok0 * NCOLS + n0;
        float* o1 = out + (size_t)tok1 * NCOLS + n0;
#pragma unroll
        for (int ni = 0; ni < 8; ni++) {
            const int col = wn + ni * 8 + cc;
            const float b0 = brow[col], b1 = brow[col + 1];
            if (tok0 >= 0) {
                atomicAdd(o0 + col,     w0 * (acc[mi][ni][0] + b0));
                atomicAdd(o0 + col + 1, w0 * (acc[mi][ni][1] + b1));
            }
            if (tok1 >= 0) {
                atomicAdd(o1 + col,     w1 * (acc[mi][ni][2] + b0));
                atomicAdd(o1 + col + 1, w1 * (acc[mi][ni][3] + b1));
            }
        }
    }
}

// ---------------- 8. aux loss ----------------
__global__ void aux_k(float* __restrict__ out, int out_size) {
    __shared__ float red[256];
    float local[NEXP];
#pragma unroll
    for (int e = 0; e < NEXP; e++) local[e] = 0.f;
    for (int t = threadIdx.x; t < NTOK; t += 256)
#pragma unroll
        for (int e = 0; e < NEXP; e++) local[e] += g_probs[t * NEXP + e];
    float aux = 0.f;
    for (int e = 0; e < NEXP; e++) {
        red[threadIdx.x] = local[e];
        __syncthreads();
        for (int s = 128; s; s >>= 1) {
            if (threadIdx.x < s) red[threadIdx.x] += red[threadIdx.x + s];
            __syncthreads();
        }
        if (threadIdx.x == 0)
            aux += ((float)g_counts[e] / (float)NTOK) * (red[0] / (float)NTOK);
        __syncthreads();
    }
    if (threadIdx.x == 0 && out_size > NTOK * D_IN)
        out[NTOK * D_IN] = (float)NEXP * aux;
}

// ---------------- launch (serial, single stream) ----------
extern "C" void kernel_launch(void* const* d_in, const int* in_sizes, int n_in,
                              void* d_out, int out_size) {
    const float* x    = (const float*)d_in[0];
    const float* Wg   = (const float*)d_in[1];
    const float* fc1w = (const float*)d_in[2];
    const float* fc1b = (const float*)d_in[3];
    const float* fc2w = (const float*)d_in[4];
    const float* fc2b = (const float*)d_in[5];
    float* out = (float*)d_out;

    cudaFuncSetAttribute(gemm1_fused, cudaFuncAttributeMaxDynamicSharedMemorySize, SMEM_GEMM);
    cudaFuncSetAttribute(gemm2_mma,   cudaFuncAttributeMaxDynamicSharedMemorySize, SMEM_GEMM);

    init_k<<<(PMAX + 255) / 256, 256>>>();
    zero_out_k<<<(out_size + 255) / 256, 256>>>(out, out_size);
    gate_k<<<NTOK / 8, 256>>>(x, Wg);
    off_k<<<1, 32>>>();
    scatter_k<<<(NTOK * 2 + 255) / 256, 256>>>();
    gatherx_k<<<PMAX, 256>>>(x);
    {
        size_t tot4 = (size_t)NEXP * H2 * D_IN / 4 + (size_t)NEXP * D_IN * HID / 4;
        conv_all<<<(unsigned)((tot4 + 255) / 256), 256>>>(fc1w, fc2w);
    }

    gemm1_fused<<<dim3(HID / 128, PMAX / TM), 256, SMEM_GEMM>>>(fc1b);
    gemm2_mma  <<<dim3(D_IN / 256, PMAX / TM), 256, SMEM_GEMM>>>(fc2b, out);

    aux_k<<<1, 256>>>(out, out_size);
}